// round 7
// baseline (speedup 1.0000x reference)
#include <cuda_runtime.h>
#include <cuda_fp16.h>
#include <math.h>
#include <stdint.h>

// ---------------- problem constants ----------------
#define NTOK   8192          // B*S = 16*512
#define EDIM   1024
#define NHEAD  16
#define HDIM   64
#define NST    6
#define NROWS  (NST*NTOK)    // 49152
#define HIDD   1024
#define LN_EPS 1e-5f

// ---------------- scratch (device globals; no allocs allowed) ----------------
__device__ __half g_Qh[(size_t)NROWS * EDIM];
__device__ __half g_Kh[(size_t)NROWS * EDIM];
__device__ __half g_Vh[(size_t)NROWS * EDIM];
__device__ float  g_ATT[(size_t)NROWS * EDIM];
__device__ __half g_STh[(size_t)NROWS * EDIM];
__device__ __half g_CTXh[(size_t)NROWS * EDIM];
__device__ __half g_FUSEDh[(size_t)NTOK * EDIM];
__device__ __half g_Wqh[(size_t)EDIM * EDIM];
__device__ __half g_Wkh[(size_t)EDIM * EDIM];
__device__ __half g_Wvh[(size_t)EDIM * EDIM];
__device__ __half g_Woh[(size_t)EDIM * EDIM];
__device__ __half g_Wfh[(size_t)HIDD * EDIM];

// ---------------- helpers ----------------
__device__ __forceinline__ uint32_t smem_u32(const void* p) {
    uint32_t a;
    asm("{ .reg .u64 t; cvta.to.shared.u64 t, %1; cvt.u32.u64 %0, t; }" : "=r"(a) : "l"(p));
    return a;
}

__device__ __forceinline__ void cp_async16(uint32_t dst, const void* src) {
    asm volatile("cp.async.cg.shared.global [%0], [%1], 16;"
                 :: "r"(dst), "l"(src) : "memory");
}

__device__ __forceinline__ void ldsm_x4(uint32_t* r, uint32_t addr) {
    asm volatile("ldmatrix.sync.aligned.m8n8.x4.shared.b16 {%0,%1,%2,%3}, [%4];"
                 : "=r"(r[0]), "=r"(r[1]), "=r"(r[2]), "=r"(r[3]) : "r"(addr));
}

__device__ __forceinline__ void mma_fp16(float* c, const uint32_t* a, const uint32_t* b) {
    asm volatile(
        "mma.sync.aligned.m16n8k16.row.col.f32.f16.f16.f32 "
        "{%0,%1,%2,%3}, {%4,%5,%6,%7}, {%8,%9}, {%0,%1,%2,%3};"
        : "+f"(c[0]), "+f"(c[1]), "+f"(c[2]), "+f"(c[3])
        : "r"(a[0]), "r"(a[1]), "r"(a[2]), "r"(a[3]), "r"(b[0]), "r"(b[1]));
}

__device__ __forceinline__ uint32_t sw128(uint32_t byte) {
    return byte ^ ((byte >> 3) & 0x70);
}

// ---------------- fp32 -> fp16 conversion (vectorized) ----------------
__global__ __launch_bounds__(256)
void f2h_kernel(const float4* __restrict__ src, uint2* __restrict__ dst, int n4)
{
    int i = blockIdx.x * blockDim.x + threadIdx.x;
    if (i < n4) {
        float4 v = src[i];
        __half2 lo = __floats2half2_rn(v.x, v.y);
        __half2 hi = __floats2half2_rn(v.z, v.w);
        dst[i] = make_uint2(*reinterpret_cast<uint32_t*>(&lo),
                            *reinterpret_cast<uint32_t*>(&hi));
    }
}

// ---------------- FP16 tensor-core GEMM ----------------
// C[M,Nc] = A[M,K] @ B[Nc,K]^T + bias[Nc], A/B fp16, C fp32 or fp16 (OutT).
// Block 128x128, BK=64 halves (128B rows, SW128), 256 threads = 8 warps (2x4),
// warp tile 64x32, 3-stage cp.async pipeline, ldmatrix fragments.
#define STG_BYTES 16384                      // 128 rows * 128 B
#define NSTAGE    3
#define GEMMH_SMEM (1024 + NSTAGE * 2 * STG_BYTES)

extern __shared__ char dynsmem[];

template <typename OutT>
__global__ __launch_bounds__(256)
void gemm_h(const __half* __restrict__ A, const __half* __restrict__ Bw,
            const float* __restrict__ bias, OutT* __restrict__ C,
            int M, int Nc, int Kd)
{
    const int tid  = threadIdx.x;
    const int warp = tid >> 5;
    const int lane = tid & 31;

    const int bm = blockIdx.y * 128;
    const int bn = blockIdx.x * 128;
    const int wm = (warp >> 2) * 64;
    const int wn = (warp & 3) * 32;

    uint32_t sbase = (smem_u32(dynsmem) + 1023u) & ~1023u;
    const uint32_t sA = sbase;                        // NSTAGE x 16KB
    const uint32_t sB = sbase + NSTAGE * STG_BYTES;   // NSTAGE x 16KB

    float acc[4][4][4];
    #pragma unroll
    for (int mt = 0; mt < 4; mt++)
        #pragma unroll
        for (int nt = 0; nt < 4; nt++)
            #pragma unroll
            for (int r = 0; r < 4; r++) acc[mt][nt][r] = 0.f;

    const int nstg = Kd / 64;

    const int a_row_in = lane & 15;
    const int a_ch     = lane >> 4;
    const int b_n_in = (lane & 7) + ((lane >> 4) & 1) * 8;
    const int b_ch   = (lane >> 3) & 1;

    auto load_stage = [&](int s, int buf) {
        const uint32_t da = sA + buf * STG_BYTES;
        const uint32_t db = sB + buf * STG_BYTES;
        #pragma unroll
        for (int i = 0; i < 4; i++) {
            int c = tid + i * 256;
            int row = c >> 3, col16 = c & 7;
            uint32_t sw = sw128(row * 128 + col16 * 16);
            const __half* ga = A  + (size_t)(bm + row) * Kd + s * 64 + col16 * 8;
            const __half* gb = Bw + (size_t)(bn + row) * Kd + s * 64 + col16 * 8;
            cp_async16(da + sw, ga);
            cp_async16(db + sw, gb);
        }
        asm volatile("cp.async.commit_group;" ::: "memory");
    };

    load_stage(0, 0);
    load_stage(1, 1);

    for (int s = 0; s < nstg; s++) {
        const int buf = s % NSTAGE;
        asm volatile("cp.async.wait_group 1;" ::: "memory");
        __syncthreads();

        if (s + 2 < nstg) load_stage(s + 2, (s + 2) % NSTAGE);

        const uint32_t abuf = sA + buf * STG_BYTES;
        const uint32_t bbuf = sB + buf * STG_BYTES;

        #pragma unroll
        for (int ks = 0; ks < 4; ks++) {            // four k16 steps per stage
            uint32_t af[4][4], bfr[2][4];
            #pragma unroll
            for (int mt = 0; mt < 4; mt++) {
                uint32_t byte = (uint32_t)(wm + mt * 16 + a_row_in) * 128
                              + ks * 32 + a_ch * 16;
                ldsm_x4(af[mt], abuf + sw128(byte));
            }
            #pragma unroll
            for (int nt2 = 0; nt2 < 2; nt2++) {
                uint32_t byte = (uint32_t)(wn + nt2 * 16 + b_n_in) * 128
                              + ks * 32 + b_ch * 16;
                ldsm_x4(bfr[nt2], bbuf + sw128(byte));
            }
            #pragma unroll
            for (int mt = 0; mt < 4; mt++)
                #pragma unroll
                for (int nt = 0; nt < 4; nt++)
                    mma_fp16(acc[mt][nt], af[mt], &bfr[nt >> 1][(nt & 1) * 2]);
        }
    }

    // epilogue: bias + store
    const int g = lane >> 2;
    const int t = lane & 3;
    #pragma unroll
    for (int mt = 0; mt < 4; mt++) {
        int r = bm + wm + mt * 16 + g;
        #pragma unroll
        for (int nt = 0; nt < 4; nt++) {
            int cc = bn + wn + nt * 8 + 2 * t;
            float bi0 = bias[cc], bi1 = bias[cc + 1];
            float v00 = acc[mt][nt][0] + bi0, v01 = acc[mt][nt][1] + bi1;
            float v10 = acc[mt][nt][2] + bi0, v11 = acc[mt][nt][3] + bi1;
            if constexpr (sizeof(OutT) == 4) {
                *reinterpret_cast<float2*>(&C[(size_t)r * Nc + cc]) = make_float2(v00, v01);
                *reinterpret_cast<float2*>(&C[(size_t)(r + 8) * Nc + cc]) = make_float2(v10, v11);
            } else {
                __half2 h0 = __floats2half2_rn(v00, v01);
                __half2 h1 = __floats2half2_rn(v10, v11);
                *reinterpret_cast<__half2*>(&C[(size_t)r * Nc + cc])       = h0;
                *reinterpret_cast<__half2*>(&C[(size_t)(r + 8) * Nc + cc]) = h1;
            }
        }
    }
}

// ---------------- tiny 6x6 attention per (token, head) ----------------
// reads fp16 Q/K/V, writes fp16 CTX (consumed by Wo GEMM)
__global__ __launch_bounds__(256)
void attn_kernel(const __half* __restrict__ Q, const __half* __restrict__ Kb,
                 const __half* __restrict__ V, __half* __restrict__ CTX)
{
    const int n    = blockIdx.x;
    const int tid  = threadIdx.x;
    const int warp = tid >> 5;
    const int lane = tid & 31;

    __shared__ float sq[NST][512];
    __shared__ float sk[NST][512];
    __shared__ float sv[NST][512];
    __shared__ float ssc[8][40];

    for (int pass = 0; pass < 2; pass++) {
        const int coff = pass * 512;
        __syncthreads();
        for (int idx = tid; idx < NST * 256; idx += 256) {
            int j = idx >> 8, e2 = (idx & 255) * 2;
            size_t gofs = ((size_t)j * NTOK + n) * EDIM + coff + e2;
            __half2 q2 = *reinterpret_cast<const __half2*>(Q + gofs);
            __half2 k2 = *reinterpret_cast<const __half2*>(Kb + gofs);
            __half2 v2 = *reinterpret_cast<const __half2*>(V + gofs);
            float2 qf = __half22float2(q2);
            float2 kf = __half22float2(k2);
            float2 vf = __half22float2(v2);
            sq[j][e2] = qf.x; sq[j][e2 + 1] = qf.y;
            sk[j][e2] = kf.x; sk[j][e2 + 1] = kf.y;
            sv[j][e2] = vf.x; sv[j][e2 + 1] = vf.y;
        }
        __syncthreads();

        const int h  = pass * 8 + warp;
        const int lc = warp * HDIM;

        for (int p = lane; p < 36; p += 32) {
            int qi = p / 6, ki = p % 6;
            float s = 0.f;
            #pragma unroll
            for (int d = 0; d < HDIM; d++)
                s += sq[qi][lc + d] * sk[ki][lc + d];
            ssc[warp][p] = s * 0.125f;
        }
        __syncwarp();

        if (lane < 6) {
            float row[6], m = -1e30f;
            #pragma unroll
            for (int kk = 0; kk < 6; kk++) { row[kk] = ssc[warp][lane * 6 + kk]; m = fmaxf(m, row[kk]); }
            float s = 0.f;
            #pragma unroll
            for (int kk = 0; kk < 6; kk++) { row[kk] = __expf(row[kk] - m); s += row[kk]; }
            float inv = 1.f / s;
            #pragma unroll
            for (int kk = 0; kk < 6; kk++) ssc[warp][lane * 6 + kk] = row[kk] * inv;
        }
        __syncwarp();

        for (int o = lane; o < NST * HDIM; o += 32) {
            int qi = o >> 6, d = o & 63;
            float c = 0.f;
            #pragma unroll
            for (int kk = 0; kk < 6; kk++)
                c += ssc[warp][qi * 6 + kk] * sv[kk][lc + d];
            CTX[((size_t)qi * NTOK + n) * EDIM + h * HDIM + d] = __float2half_rn(c);
        }
    }
}

// ---------------- block reduction helper (256 threads) ----------------
__device__ __forceinline__ float block_sum(float v, float* sbuf)
{
    const int lane = threadIdx.x & 31;
    const int wid  = threadIdx.x >> 5;
    #pragma unroll
    for (int o = 16; o > 0; o >>= 1) v += __shfl_xor_sync(0xffffffffu, v, o);
    if (lane == 0) sbuf[wid] = v;
    __syncthreads();
    if (wid == 0) {
        float r = (lane < 8) ? sbuf[lane] : 0.f;
        #pragma unroll
        for (int o = 4; o > 0; o >>= 1) r += __shfl_xor_sync(0xffffffffu, r, o);
        if (lane == 0) sbuf[0] = r;
    }
    __syncthreads();
    float r = sbuf[0];
    __syncthreads();
    return r;
}

// ---------------- residual + LN1 + softmax(fusion_w)-weighted sum (-> fp16) ----------------
__global__ __launch_bounds__(256)
void ln1_fuse_kernel(const float* __restrict__ ATT, const float* __restrict__ ST,
                     const float* __restrict__ g1, const float* __restrict__ b1,
                     const float* __restrict__ fw, __half* __restrict__ FUSED)
{
    __shared__ float sbuf[32];
    const int n = blockIdx.x, tid = threadIdx.x;

    float w[6];
    {
        float m = -1e30f;
        #pragma unroll
        for (int j = 0; j < 6; j++) { w[j] = fw[j]; m = fmaxf(m, w[j]); }
        float s = 0.f;
        #pragma unroll
        for (int j = 0; j < 6; j++) { w[j] = __expf(w[j] - m); s += w[j]; }
        float inv = 1.f / s;
        #pragma unroll
        for (int j = 0; j < 6; j++) w[j] *= inv;
    }

    float accv[4] = {0.f, 0.f, 0.f, 0.f};
    for (int j = 0; j < 6; j++) {
        size_t base = ((size_t)j * NTOK + n) * EDIM;
        float x[4], lsum = 0.f;
        #pragma unroll
        for (int tq = 0; tq < 4; tq++) {
            int e = tq * 256 + tid;
            x[tq] = ATT[base + e] + ST[base + e];
            lsum += x[tq];
        }
        float mean = block_sum(lsum, sbuf) * (1.f / EDIM);
        float lvar = 0.f;
        #pragma unroll
        for (int tq = 0; tq < 4; tq++) { float d = x[tq] - mean; lvar += d * d; }
        float var = block_sum(lvar, sbuf) * (1.f / EDIM);
        float inv = rsqrtf(var + LN_EPS);
        #pragma unroll
        for (int tq = 0; tq < 4; tq++) {
            int e = tq * 256 + tid;
            accv[tq] += w[j] * ((x[tq] - mean) * inv * g1[e] + b1[e]);
        }
    }
    #pragma unroll
    for (int tq = 0; tq < 4; tq++)
        FUSED[(size_t)n * EDIM + tq * 256 + tid] = __float2half_rn(accv[tq]);
}

// ---------------- LeakyReLU + LN2 (in-place on d_out) ----------------
__global__ __launch_bounds__(256)
void lrelu_ln2_kernel(float* __restrict__ O, const float* __restrict__ g2,
                      const float* __restrict__ b2)
{
    __shared__ float sbuf[32];
    const int n = blockIdx.x, tid = threadIdx.x;
    size_t base = (size_t)n * HIDD;

    float x[4], lsum = 0.f;
    #pragma unroll
    for (int tq = 0; tq < 4; tq++) {
        int e = tq * 256 + tid;
        float v = O[base + e];
        v = (v >= 0.f) ? v : 0.01f * v;
        x[tq] = v; lsum += v;
    }
    float mean = block_sum(lsum, sbuf) * (1.f / HIDD);
    float lvar = 0.f;
    #pragma unroll
    for (int tq = 0; tq < 4; tq++) { float d = x[tq] - mean; lvar += d * d; }
    float var = block_sum(lvar, sbuf) * (1.f / HIDD);
    float inv = rsqrtf(var + LN_EPS);
    #pragma unroll
    for (int tq = 0; tq < 4; tq++) {
        int e = tq * 256 + tid;
        O[base + e] = (x[tq] - mean) * inv * g2[e] + b2[e];
    }
}

// ---------------- launch ----------------
extern "C" void kernel_launch(void* const* d_in, const int* in_sizes, int n_in,
                              void* d_out, int out_size)
{
    const float* st = (const float*)d_in[0];
    const float* Wq = (const float*)d_in[1];  const float* bq = (const float*)d_in[2];
    const float* Wk = (const float*)d_in[3];  const float* bk = (const float*)d_in[4];
    const float* Wv = (const float*)d_in[5];  const float* bv = (const float*)d_in[6];
    const float* Wo = (const float*)d_in[7];  const float* bo = (const float*)d_in[8];
    const float* g1 = (const float*)d_in[9];  const float* b1 = (const float*)d_in[10];
    const float* fw = (const float*)d_in[11];
    const float* Wf = (const float*)d_in[12]; const float* bf = (const float*)d_in[13];
    const float* g2 = (const float*)d_in[14]; const float* b2 = (const float*)d_in[15];
    float* out = (float*)d_out;

    float *ATTb;
    __half *Qh, *Kh, *Vh, *STh, *CTXh, *FUSh, *Wqh, *Wkh, *Wvh, *Woh, *Wfh;
    cudaGetSymbolAddress((void**)&Qh,   g_Qh);
    cudaGetSymbolAddress((void**)&Kh,   g_Kh);
    cudaGetSymbolAddress((void**)&Vh,   g_Vh);
    cudaGetSymbolAddress((void**)&ATTb, g_ATT);
    cudaGetSymbolAddress((void**)&STh,  g_STh);
    cudaGetSymbolAddress((void**)&CTXh, g_CTXh);
    cudaGetSymbolAddress((void**)&FUSh, g_FUSEDh);
    cudaGetSymbolAddress((void**)&Wqh,  g_Wqh);
    cudaGetSymbolAddress((void**)&Wkh,  g_Wkh);
    cudaGetSymbolAddress((void**)&Wvh,  g_Wvh);
    cudaGetSymbolAddress((void**)&Woh,  g_Woh);
    cudaGetSymbolAddress((void**)&Wfh,  g_Wfh);

    cudaFuncSetAttribute(gemm_h<__half>, cudaFuncAttributeMaxDynamicSharedMemorySize,
                         GEMMH_SMEM);
    cudaFuncSetAttribute(gemm_h<float>, cudaFuncAttributeMaxDynamicSharedMemorySize,
                         GEMMH_SMEM);

    // ---- fp32 -> fp16 conversions ----
    {
        int n4 = (NROWS * EDIM) / 4;
        f2h_kernel<<<(n4 + 255) / 256, 256>>>((const float4*)st, (uint2*)STh, n4);
        int w4 = (EDIM * EDIM) / 4;
        f2h_kernel<<<(w4 + 255) / 256, 256>>>((const float4*)Wq, (uint2*)Wqh, w4);
        f2h_kernel<<<(w4 + 255) / 256, 256>>>((const float4*)Wk, (uint2*)Wkh, w4);
        f2h_kernel<<<(w4 + 255) / 256, 256>>>((const float4*)Wv, (uint2*)Wvh, w4);
        f2h_kernel<<<(w4 + 255) / 256, 256>>>((const float4*)Wo, (uint2*)Woh, w4);
        int f4 = (HIDD * EDIM) / 4;
        f2h_kernel<<<(f4 + 255) / 256, 256>>>((const float4*)Wf, (uint2*)Wfh, f4);
    }

    dim3 blk(256);
    dim3 gproj(EDIM / 128, NROWS / 128);   // (8, 384)
    gemm_h<__half><<<gproj, blk, GEMMH_SMEM>>>(STh, Wqh, bq, Qh, NROWS, EDIM, EDIM);
    gemm_h<__half><<<gproj, blk, GEMMH_SMEM>>>(STh, Wkh, bk, Kh, NROWS, EDIM, EDIM);
    gemm_h<__half><<<gproj, blk, GEMMH_SMEM>>>(STh, Wvh, bv, Vh, NROWS, EDIM, EDIM);

    attn_kernel<<<NTOK, 256>>>(Qh, Kh, Vh, CTXh);

    gemm_h<float><<<gproj, blk, GEMMH_SMEM>>>(CTXh, Woh, bo, ATTb, NROWS, EDIM, EDIM);

    ln1_fuse_kernel<<<NTOK, 256>>>(ATTb, st, g1, b1, fw, FUSh);

    dim3 gmlp(HIDD / 128, NTOK / 128);     // (8, 64)
    gemm_h<float><<<gmlp, blk, GEMMH_SMEM>>>(FUSh, Wfh, bf, out, NTOK, HIDD, EDIM);

    lrelu_ln2_kernel<<<NTOK, 256>>>(out, g2, b2);
}

// round 8
// speedup vs baseline: 1.3674x; 1.3674x over previous
#include <cuda_runtime.h>
#include <cuda_fp16.h>
#include <math.h>
#include <stdint.h>

// ---------------- problem constants ----------------
#define NTOK   8192          // B*S = 16*512
#define EDIM   1024
#define NHEAD  16
#define HDIM   64
#define NST    6
#define NROWS  (NST*NTOK)    // 49152
#define HIDD   1024
#define LN_EPS 1e-5f

// ---------------- scratch (device globals; no allocs allowed) ----------------
__device__ __half g_Qh[(size_t)NROWS * EDIM];
__device__ __half g_Kh[(size_t)NROWS * EDIM];
__device__ __half g_Vh[(size_t)NROWS * EDIM];
__device__ float  g_ATT[(size_t)NROWS * EDIM];
__device__ __half g_STh[(size_t)NROWS * EDIM];
__device__ __half g_CTXh[(size_t)NROWS * EDIM];
__device__ __half g_FUSEDh[(size_t)NTOK * EDIM];
__device__ __half g_Wqh[(size_t)EDIM * EDIM];
__device__ __half g_Wkh[(size_t)EDIM * EDIM];
__device__ __half g_Wvh[(size_t)EDIM * EDIM];
__device__ __half g_Woh[(size_t)EDIM * EDIM];
__device__ __half g_Wfh[(size_t)HIDD * EDIM];

// ---------------- helpers ----------------
__device__ __forceinline__ uint32_t smem_u32(const void* p) {
    uint32_t a;
    asm("{ .reg .u64 t; cvta.to.shared.u64 t, %1; cvt.u32.u64 %0, t; }" : "=r"(a) : "l"(p));
    return a;
}

__device__ __forceinline__ void cp_async16(uint32_t dst, const void* src) {
    asm volatile("cp.async.cg.shared.global [%0], [%1], 16;"
                 :: "r"(dst), "l"(src) : "memory");
}

__device__ __forceinline__ void ldsm_x4(uint32_t* r, uint32_t addr) {
    asm volatile("ldmatrix.sync.aligned.m8n8.x4.shared.b16 {%0,%1,%2,%3}, [%4];"
                 : "=r"(r[0]), "=r"(r[1]), "=r"(r[2]), "=r"(r[3]) : "r"(addr));
}

__device__ __forceinline__ void mma_fp16(float* c, const uint32_t* a, const uint32_t* b) {
    asm volatile(
        "mma.sync.aligned.m16n8k16.row.col.f32.f16.f16.f32 "
        "{%0,%1,%2,%3}, {%4,%5,%6,%7}, {%8,%9}, {%0,%1,%2,%3};"
        : "+f"(c[0]), "+f"(c[1]), "+f"(c[2]), "+f"(c[3])
        : "r"(a[0]), "r"(a[1]), "r"(a[2]), "r"(a[3]), "r"(b[0]), "r"(b[1]));
}

__device__ __forceinline__ uint32_t sw128(uint32_t byte) {
    return byte ^ ((byte >> 3) & 0x70);
}

// ---------------- fp32 -> fp16 conversion (vectorized) ----------------
__global__ __launch_bounds__(256)
void f2h_kernel(const float4* __restrict__ src, uint2* __restrict__ dst, int n4)
{
    int i = blockIdx.x * blockDim.x + threadIdx.x;
    if (i < n4) {
        float4 v = src[i];
        __half2 lo = __floats2half2_rn(v.x, v.y);
        __half2 hi = __floats2half2_rn(v.z, v.w);
        dst[i] = make_uint2(*reinterpret_cast<uint32_t*>(&lo),
                            *reinterpret_cast<uint32_t*>(&hi));
    }
}

// ---------------- FP16 tensor-core GEMM (round-6 proven 2-stage pipeline) ----------------
// C[M,Nc] = A[M,K] @ B[Nc,K]^T + bias[Nc], A/B fp16, OutT = fp32 or fp16.
// Block 128x128, BK=64 halves (128B rows, SW128), 256 threads = 8 warps (2x4),
// warp tile 64x32, double-buffered cp.async pipeline, ldmatrix fragments.
#define STG_BYTES 16384                      // 128 rows * 128 B
#define GEMMH_SMEM (1024 + 4 * STG_BYTES)    // align pad + 2 stages x (A+B)

extern __shared__ char dynsmem[];

template <typename OutT>
__global__ __launch_bounds__(256)
void gemm_h(const __half* __restrict__ A, const __half* __restrict__ Bw,
            const float* __restrict__ bias, OutT* __restrict__ C,
            int M, int Nc, int Kd)
{
    const int tid  = threadIdx.x;
    const int warp = tid >> 5;
    const int lane = tid & 31;

    const int bm = blockIdx.y * 128;
    const int bn = blockIdx.x * 128;
    const int wm = (warp >> 2) * 64;
    const int wn = (warp & 3) * 32;

    uint32_t sbase = (smem_u32(dynsmem) + 1023u) & ~1023u;
    const uint32_t sA = sbase;                 // 2 x 16KB
    const uint32_t sB = sbase + 2 * STG_BYTES; // 2 x 16KB

    float acc[4][4][4];
    #pragma unroll
    for (int mt = 0; mt < 4; mt++)
        #pragma unroll
        for (int nt = 0; nt < 4; nt++)
            #pragma unroll
            for (int r = 0; r < 4; r++) acc[mt][nt][r] = 0.f;

    const int nstg = Kd / 64;

    const int a_row_in = lane & 15;
    const int a_ch     = lane >> 4;
    const int b_n_in = (lane & 7) + ((lane >> 4) & 1) * 8;
    const int b_ch   = (lane >> 3) & 1;

    auto load_stage = [&](int s, int buf) {
        const uint32_t da = sA + buf * STG_BYTES;
        const uint32_t db = sB + buf * STG_BYTES;
        #pragma unroll
        for (int i = 0; i < 4; i++) {
            int c = tid + i * 256;
            int row = c >> 3, col16 = c & 7;
            uint32_t sw = sw128(row * 128 + col16 * 16);
            const __half* ga = A  + (size_t)(bm + row) * Kd + s * 64 + col16 * 8;
            const __half* gb = Bw + (size_t)(bn + row) * Kd + s * 64 + col16 * 8;
            cp_async16(da + sw, ga);
            cp_async16(db + sw, gb);
        }
        asm volatile("cp.async.commit_group;" ::: "memory");
    };

    load_stage(0, 0);

    for (int s = 0; s < nstg; s++) {
        const int buf = s & 1;
        if (s + 1 < nstg) {
            load_stage(s + 1, buf ^ 1);
            asm volatile("cp.async.wait_group 1;" ::: "memory");
        } else {
            asm volatile("cp.async.wait_group 0;" ::: "memory");
        }
        __syncthreads();

        const uint32_t abuf = sA + buf * STG_BYTES;
        const uint32_t bbuf = sB + buf * STG_BYTES;

        #pragma unroll
        for (int ks = 0; ks < 4; ks++) {            // four k16 steps per stage
            uint32_t af[4][4], bfr[2][4];
            #pragma unroll
            for (int mt = 0; mt < 4; mt++) {
                uint32_t byte = (uint32_t)(wm + mt * 16 + a_row_in) * 128
                              + ks * 32 + a_ch * 16;
                ldsm_x4(af[mt], abuf + sw128(byte));
            }
            #pragma unroll
            for (int nt2 = 0; nt2 < 2; nt2++) {
                uint32_t byte = (uint32_t)(wn + nt2 * 16 + b_n_in) * 128
                              + ks * 32 + b_ch * 16;
                ldsm_x4(bfr[nt2], bbuf + sw128(byte));
            }
            #pragma unroll
            for (int mt = 0; mt < 4; mt++)
                #pragma unroll
                for (int nt = 0; nt < 4; nt++)
                    mma_fp16(acc[mt][nt], af[mt], &bfr[nt >> 1][(nt & 1) * 2]);
        }
        __syncthreads();
    }

    // epilogue: bias + store
    const int g = lane >> 2;
    const int t = lane & 3;
    #pragma unroll
    for (int mt = 0; mt < 4; mt++) {
        int r = bm + wm + mt * 16 + g;
        #pragma unroll
        for (int nt = 0; nt < 4; nt++) {
            int cc = bn + wn + nt * 8 + 2 * t;
            float bi0 = bias[cc], bi1 = bias[cc + 1];
            float v00 = acc[mt][nt][0] + bi0, v01 = acc[mt][nt][1] + bi1;
            float v10 = acc[mt][nt][2] + bi0, v11 = acc[mt][nt][3] + bi1;
            if constexpr (sizeof(OutT) == 4) {
                *reinterpret_cast<float2*>(&C[(size_t)r * Nc + cc]) = make_float2(v00, v01);
                *reinterpret_cast<float2*>(&C[(size_t)(r + 8) * Nc + cc]) = make_float2(v10, v11);
            } else {
                __half2 h0 = __floats2half2_rn(v00, v01);
                __half2 h1 = __floats2half2_rn(v10, v11);
                *reinterpret_cast<__half2*>(&C[(size_t)r * Nc + cc])       = h0;
                *reinterpret_cast<__half2*>(&C[(size_t)(r + 8) * Nc + cc]) = h1;
            }
        }
    }
}

// ---------------- tiny 6x6 attention per (token, head) ----------------
// reads fp16 Q/K/V, writes fp16 CTX (consumed by Wo GEMM)
__global__ __launch_bounds__(256)
void attn_kernel(const __half* __restrict__ Q, const __half* __restrict__ Kb,
                 const __half* __restrict__ V, __half* __restrict__ CTX)
{
    const int n    = blockIdx.x;
    const int tid  = threadIdx.x;
    const int warp = tid >> 5;
    const int lane = tid & 31;

    __shared__ float sq[NST][512];
    __shared__ float sk[NST][512];
    __shared__ float sv[NST][512];
    __shared__ float ssc[8][40];

    for (int pass = 0; pass < 2; pass++) {
        const int coff = pass * 512;
        __syncthreads();
        for (int idx = tid; idx < NST * 256; idx += 256) {
            int j = idx >> 8, e2 = (idx & 255) * 2;
            size_t gofs = ((size_t)j * NTOK + n) * EDIM + coff + e2;
            __half2 q2 = *reinterpret_cast<const __half2*>(Q + gofs);
            __half2 k2 = *reinterpret_cast<const __half2*>(Kb + gofs);
            __half2 v2 = *reinterpret_cast<const __half2*>(V + gofs);
            float2 qf = __half22float2(q2);
            float2 kf = __half22float2(k2);
            float2 vf = __half22float2(v2);
            sq[j][e2] = qf.x; sq[j][e2 + 1] = qf.y;
            sk[j][e2] = kf.x; sk[j][e2 + 1] = kf.y;
            sv[j][e2] = vf.x; sv[j][e2 + 1] = vf.y;
        }
        __syncthreads();

        const int h  = pass * 8 + warp;
        const int lc = warp * HDIM;

        for (int p = lane; p < 36; p += 32) {
            int qi = p / 6, ki = p % 6;
            float s = 0.f;
            #pragma unroll
            for (int d = 0; d < HDIM; d++)
                s += sq[qi][lc + d] * sk[ki][lc + d];
            ssc[warp][p] = s * 0.125f;
        }
        __syncwarp();

        if (lane < 6) {
            float row[6], m = -1e30f;
            #pragma unroll
            for (int kk = 0; kk < 6; kk++) { row[kk] = ssc[warp][lane * 6 + kk]; m = fmaxf(m, row[kk]); }
            float s = 0.f;
            #pragma unroll
            for (int kk = 0; kk < 6; kk++) { row[kk] = __expf(row[kk] - m); s += row[kk]; }
            float inv = 1.f / s;
            #pragma unroll
            for (int kk = 0; kk < 6; kk++) ssc[warp][lane * 6 + kk] = row[kk] * inv;
        }
        __syncwarp();

        for (int o = lane; o < NST * HDIM; o += 32) {
            int qi = o >> 6, d = o & 63;
            float c = 0.f;
            #pragma unroll
            for (int kk = 0; kk < 6; kk++)
                c += ssc[warp][qi * 6 + kk] * sv[kk][lc + d];
            CTX[((size_t)qi * NTOK + n) * EDIM + h * HDIM + d] = __float2half_rn(c);
        }
    }
}

// ---------------- block reduction helper (256 threads) ----------------
__device__ __forceinline__ float block_sum(float v, float* sbuf)
{
    const int lane = threadIdx.x & 31;
    const int wid  = threadIdx.x >> 5;
    #pragma unroll
    for (int o = 16; o > 0; o >>= 1) v += __shfl_xor_sync(0xffffffffu, v, o);
    if (lane == 0) sbuf[wid] = v;
    __syncthreads();
    if (wid == 0) {
        float r = (lane < 8) ? sbuf[lane] : 0.f;
        #pragma unroll
        for (int o = 4; o > 0; o >>= 1) r += __shfl_xor_sync(0xffffffffu, r, o);
        if (lane == 0) sbuf[0] = r;
    }
    __syncthreads();
    float r = sbuf[0];
    __syncthreads();
    return r;
}

// ---------------- residual + LN1 + softmax(fusion_w)-weighted sum (-> fp16) ----------------
__global__ __launch_bounds__(256)
void ln1_fuse_kernel(const float* __restrict__ ATT, const float* __restrict__ ST,
                     const float* __restrict__ g1, const float* __restrict__ b1,
                     const float* __restrict__ fw, __half* __restrict__ FUSED)
{
    __shared__ float sbuf[32];
    const int n = blockIdx.x, tid = threadIdx.x;

    float w[6];
    {
        float m = -1e30f;
        #pragma unroll
        for (int j = 0; j < 6; j++) { w[j] = fw[j]; m = fmaxf(m, w[j]); }
        float s = 0.f;
        #pragma unroll
        for (int j = 0; j < 6; j++) { w[j] = __expf(w[j] - m); s += w[j]; }
        float inv = 1.f / s;
        #pragma unroll
        for (int j = 0; j < 6; j++) w[j] *= inv;
    }

    float accv[4] = {0.f, 0.f, 0.f, 0.f};
    for (int j = 0; j < 6; j++) {
        size_t base = ((size_t)j * NTOK + n) * EDIM;
        float x[4], lsum = 0.f;
        #pragma unroll
        for (int tq = 0; tq < 4; tq++) {
            int e = tq * 256 + tid;
            x[tq] = ATT[base + e] + ST[base + e];
            lsum += x[tq];
        }
        float mean = block_sum(lsum, sbuf) * (1.f / EDIM);
        float lvar = 0.f;
        #pragma unroll
        for (int tq = 0; tq < 4; tq++) { float d = x[tq] - mean; lvar += d * d; }
        float var = block_sum(lvar, sbuf) * (1.f / EDIM);
        float inv = rsqrtf(var + LN_EPS);
        #pragma unroll
        for (int tq = 0; tq < 4; tq++) {
            int e = tq * 256 + tid;
            accv[tq] += w[j] * ((x[tq] - mean) * inv * g1[e] + b1[e]);
        }
    }
    #pragma unroll
    for (int tq = 0; tq < 4; tq++)
        FUSED[(size_t)n * EDIM + tq * 256 + tid] = __float2half_rn(accv[tq]);
}

// ---------------- LeakyReLU + LN2 (in-place on d_out) ----------------
__global__ __launch_bounds__(256)
void lrelu_ln2_kernel(float* __restrict__ O, const float* __restrict__ g2,
                      const float* __restrict__ b2)
{
    __shared__ float sbuf[32];
    const int n = blockIdx.x, tid = threadIdx.x;
    size_t base = (size_t)n * HIDD;

    float x[4], lsum = 0.f;
    #pragma unroll
    for (int tq = 0; tq < 4; tq++) {
        int e = tq * 256 + tid;
        float v = O[base + e];
        v = (v >= 0.f) ? v : 0.01f * v;
        x[tq] = v; lsum += v;
    }
    float mean = block_sum(lsum, sbuf) * (1.f / HIDD);
    float lvar = 0.f;
    #pragma unroll
    for (int tq = 0; tq < 4; tq++) { float d = x[tq] - mean; lvar += d * d; }
    float var = block_sum(lvar, sbuf) * (1.f / HIDD);
    float inv = rsqrtf(var + LN_EPS);
    #pragma unroll
    for (int tq = 0; tq < 4; tq++) {
        int e = tq * 256 + tid;
        O[base + e] = (x[tq] - mean) * inv * g2[e] + b2[e];
    }
}

// ---------------- launch ----------------
extern "C" void kernel_launch(void* const* d_in, const int* in_sizes, int n_in,
                              void* d_out, int out_size)
{
    const float* st = (const float*)d_in[0];
    const float* Wq = (const float*)d_in[1];  const float* bq = (const float*)d_in[2];
    const float* Wk = (const float*)d_in[3];  const float* bk = (const float*)d_in[4];
    const float* Wv = (const float*)d_in[5];  const float* bv = (const float*)d_in[6];
    const float* Wo = (const float*)d_in[7];  const float* bo = (const float*)d_in[8];
    const float* g1 = (const float*)d_in[9];  const float* b1 = (const float*)d_in[10];
    const float* fw = (const float*)d_in[11];
    const float* Wf = (const float*)d_in[12]; const float* bf = (const float*)d_in[13];
    const float* g2 = (const float*)d_in[14]; const float* b2 = (const float*)d_in[15];
    float* out = (float*)d_out;

    float *ATTb;
    __half *Qh, *Kh, *Vh, *STh, *CTXh, *FUSh, *Wqh, *Wkh, *Wvh, *Woh, *Wfh;
    cudaGetSymbolAddress((void**)&Qh,   g_Qh);
    cudaGetSymbolAddress((void**)&Kh,   g_Kh);
    cudaGetSymbolAddress((void**)&Vh,   g_Vh);
    cudaGetSymbolAddress((void**)&ATTb, g_ATT);
    cudaGetSymbolAddress((void**)&STh,  g_STh);
    cudaGetSymbolAddress((void**)&CTXh, g_CTXh);
    cudaGetSymbolAddress((void**)&FUSh, g_FUSEDh);
    cudaGetSymbolAddress((void**)&Wqh,  g_Wqh);
    cudaGetSymbolAddress((void**)&Wkh,  g_Wkh);
    cudaGetSymbolAddress((void**)&Wvh,  g_Wvh);
    cudaGetSymbolAddress((void**)&Woh,  g_Woh);
    cudaGetSymbolAddress((void**)&Wfh,  g_Wfh);

    cudaFuncSetAttribute(gemm_h<__half>, cudaFuncAttributeMaxDynamicSharedMemorySize,
                         GEMMH_SMEM);
    cudaFuncSetAttribute(gemm_h<float>, cudaFuncAttributeMaxDynamicSharedMemorySize,
                         GEMMH_SMEM);

    // ---- fp32 -> fp16 conversions ----
    {
        int n4 = (NROWS * EDIM) / 4;
        f2h_kernel<<<(n4 + 255) / 256, 256>>>((const float4*)st, (uint2*)STh, n4);
        int w4 = (EDIM * EDIM) / 4;
        f2h_kernel<<<(w4 + 255) / 256, 256>>>((const float4*)Wq, (uint2*)Wqh, w4);
        f2h_kernel<<<(w4 + 255) / 256, 256>>>((const float4*)Wk, (uint2*)Wkh, w4);
        f2h_kernel<<<(w4 + 255) / 256, 256>>>((const float4*)Wv, (uint2*)Wvh, w4);
        f2h_kernel<<<(w4 + 255) / 256, 256>>>((const float4*)Wo, (uint2*)Woh, w4);
        int f4 = (HIDD * EDIM) / 4;
        f2h_kernel<<<(f4 + 255) / 256, 256>>>((const float4*)Wf, (uint2*)Wfh, f4);
    }

    dim3 blk(256);
    dim3 gproj(EDIM / 128, NROWS / 128);   // (8, 384)
    gemm_h<__half><<<gproj, blk, GEMMH_SMEM>>>(STh, Wqh, bq, Qh, NROWS, EDIM, EDIM);
    gemm_h<__half><<<gproj, blk, GEMMH_SMEM>>>(STh, Wkh, bk, Kh, NROWS, EDIM, EDIM);
    gemm_h<__half><<<gproj, blk, GEMMH_SMEM>>>(STh, Wvh, bv, Vh, NROWS, EDIM, EDIM);

    attn_kernel<<<NTOK, 256>>>(Qh, Kh, Vh, CTXh);

    gemm_h<float><<<gproj, blk, GEMMH_SMEM>>>(CTXh, Woh, bo, ATTb, NROWS, EDIM, EDIM);

    ln1_fuse_kernel<<<NTOK, 256>>>(ATTb, st, g1, b1, fw, FUSh);

    dim3 gmlp(HIDD / 128, NTOK / 128);     // (8, 64)
    gemm_h<float><<<gmlp, blk, GEMMH_SMEM>>>(FUSh, Wfh, bf, out, NTOK, HIDD, EDIM);

    lrelu_ln2_kernel<<<NTOK, 256>>>(out, g2, b2);
}

// round 9
// speedup vs baseline: 1.5702x; 1.1483x over previous
#include <cuda_runtime.h>
#include <cuda_fp16.h>
#include <math.h>
#include <stdint.h>

// ---------------- problem constants ----------------
#define NTOK   8192          // B*S = 16*512
#define EDIM   1024
#define NHEAD  16
#define HDIM   64
#define NST    6
#define NROWS  (NST*NTOK)    // 49152
#define HIDD   1024
#define LN_EPS 1e-5f

// ---------------- scratch (device globals; no allocs allowed) ----------------
__device__ __half g_Qh[(size_t)NROWS * EDIM];
__device__ __half g_Kh[(size_t)NROWS * EDIM];
__device__ __half g_Vh[(size_t)NROWS * EDIM];
__device__ float  g_ATT[(size_t)NROWS * EDIM];
__device__ __half g_STh[(size_t)NROWS * EDIM];
__device__ __half g_CTXh[(size_t)NROWS * EDIM];
__device__ __half g_FUSEDh[(size_t)NTOK * EDIM];
__device__ __half g_Wqh[(size_t)EDIM * EDIM];
__device__ __half g_Wkh[(size_t)EDIM * EDIM];
__device__ __half g_Wvh[(size_t)EDIM * EDIM];
__device__ __half g_Woh[(size_t)EDIM * EDIM];
__device__ __half g_Wfh[(size_t)HIDD * EDIM];

// ---------------- helpers ----------------
__device__ __forceinline__ uint32_t smem_u32(const void* p) {
    uint32_t a;
    asm("{ .reg .u64 t; cvta.to.shared.u64 t, %1; cvt.u32.u64 %0, t; }" : "=r"(a) : "l"(p));
    return a;
}

__device__ __forceinline__ void cp_async16(uint32_t dst, const void* src) {
    asm volatile("cp.async.cg.shared.global [%0], [%1], 16;"
                 :: "r"(dst), "l"(src) : "memory");
}

__device__ __forceinline__ void ldsm_x4(uint32_t* r, uint32_t addr) {
    asm volatile("ldmatrix.sync.aligned.m8n8.x4.shared.b16 {%0,%1,%2,%3}, [%4];"
                 : "=r"(r[0]), "=r"(r[1]), "=r"(r[2]), "=r"(r[3]) : "r"(addr));
}

__device__ __forceinline__ void mma_fp16(float* c, const uint32_t* a, const uint32_t* b) {
    asm volatile(
        "mma.sync.aligned.m16n8k16.row.col.f32.f16.f16.f32 "
        "{%0,%1,%2,%3}, {%4,%5,%6,%7}, {%8,%9}, {%0,%1,%2,%3};"
        : "+f"(c[0]), "+f"(c[1]), "+f"(c[2]), "+f"(c[3])
        : "r"(a[0]), "r"(a[1]), "r"(a[2]), "r"(a[3]), "r"(b[0]), "r"(b[1]));
}

__device__ __forceinline__ uint32_t sw128(uint32_t byte) {
    return byte ^ ((byte >> 3) & 0x70);
}

// ---------------- fp32 -> fp16 conversion (vectorized) ----------------
__global__ __launch_bounds__(256)
void f2h_kernel(const float4* __restrict__ src, uint2* __restrict__ dst, int n4)
{
    int i = blockIdx.x * blockDim.x + threadIdx.x;
    if (i < n4) {
        float4 v = src[i];
        __half2 lo = __floats2half2_rn(v.x, v.y);
        __half2 hi = __floats2half2_rn(v.z, v.w);
        dst[i] = make_uint2(*reinterpret_cast<uint32_t*>(&lo),
                            *reinterpret_cast<uint32_t*>(&hi));
    }
}

// ---------------- FP16 tensor-core GEMM (proven 2-stage pipeline) ----------------
// C[M,Nc] = A[M,K] @ B[Nc,K]^T + bias[Nc], A/B fp16, OutT = fp32 or fp16.
// Block 128x128, BK=64 halves (128B rows, SW128), 256 threads = 8 warps (2x4),
// warp tile 64x32, double-buffered cp.async pipeline, ldmatrix fragments.
#define STG_BYTES 16384                      // 128 rows * 128 B
#define GEMMH_SMEM (1024 + 4 * STG_BYTES)    // align pad + 2 stages x (A+B)

extern __shared__ char dynsmem[];

template <typename OutT>
__global__ __launch_bounds__(256)
void gemm_h(const __half* __restrict__ A, const __half* __restrict__ Bw,
            const float* __restrict__ bias, OutT* __restrict__ C,
            int M, int Nc, int Kd)
{
    const int tid  = threadIdx.x;
    const int warp = tid >> 5;
    const int lane = tid & 31;

    const int bm = blockIdx.y * 128;
    const int bn = blockIdx.x * 128;
    const int wm = (warp >> 2) * 64;
    const int wn = (warp & 3) * 32;

    uint32_t sbase = (smem_u32(dynsmem) + 1023u) & ~1023u;
    const uint32_t sA = sbase;                 // 2 x 16KB
    const uint32_t sB = sbase + 2 * STG_BYTES; // 2 x 16KB

    float acc[4][4][4];
    #pragma unroll
    for (int mt = 0; mt < 4; mt++)
        #pragma unroll
        for (int nt = 0; nt < 4; nt++)
            #pragma unroll
            for (int r = 0; r < 4; r++) acc[mt][nt][r] = 0.f;

    const int nstg = Kd / 64;

    const int a_row_in = lane & 15;
    const int a_ch     = lane >> 4;
    const int b_n_in = (lane & 7) + ((lane >> 4) & 1) * 8;
    const int b_ch   = (lane >> 3) & 1;

    auto load_stage = [&](int s, int buf) {
        const uint32_t da = sA + buf * STG_BYTES;
        const uint32_t db = sB + buf * STG_BYTES;
        #pragma unroll
        for (int i = 0; i < 4; i++) {
            int c = tid + i * 256;
            int row = c >> 3, col16 = c & 7;
            uint32_t sw = sw128(row * 128 + col16 * 16);
            const __half* ga = A  + (size_t)(bm + row) * Kd + s * 64 + col16 * 8;
            const __half* gb = Bw + (size_t)(bn + row) * Kd + s * 64 + col16 * 8;
            cp_async16(da + sw, ga);
            cp_async16(db + sw, gb);
        }
        asm volatile("cp.async.commit_group;" ::: "memory");
    };

    load_stage(0, 0);

    for (int s = 0; s < nstg; s++) {
        const int buf = s & 1;
        if (s + 1 < nstg) {
            load_stage(s + 1, buf ^ 1);
            asm volatile("cp.async.wait_group 1;" ::: "memory");
        } else {
            asm volatile("cp.async.wait_group 0;" ::: "memory");
        }
        __syncthreads();

        const uint32_t abuf = sA + buf * STG_BYTES;
        const uint32_t bbuf = sB + buf * STG_BYTES;

        #pragma unroll
        for (int ks = 0; ks < 4; ks++) {            // four k16 steps per stage
            uint32_t af[4][4], bfr[2][4];
            #pragma unroll
            for (int mt = 0; mt < 4; mt++) {
                uint32_t byte = (uint32_t)(wm + mt * 16 + a_row_in) * 128
                              + ks * 32 + a_ch * 16;
                ldsm_x4(af[mt], abuf + sw128(byte));
            }
            #pragma unroll
            for (int nt2 = 0; nt2 < 2; nt2++) {
                uint32_t byte = (uint32_t)(wn + nt2 * 16 + b_n_in) * 128
                              + ks * 32 + b_ch * 16;
                ldsm_x4(bfr[nt2], bbuf + sw128(byte));
            }
            #pragma unroll
            for (int mt = 0; mt < 4; mt++)
                #pragma unroll
                for (int nt = 0; nt < 4; nt++)
                    mma_fp16(acc[mt][nt], af[mt], &bfr[nt >> 1][(nt & 1) * 2]);
        }
        __syncthreads();
    }

    // epilogue: bias + store
    const int g = lane >> 2;
    const int t = lane & 3;
    #pragma unroll
    for (int mt = 0; mt < 4; mt++) {
        int r = bm + wm + mt * 16 + g;
        #pragma unroll
        for (int nt = 0; nt < 4; nt++) {
            int cc = bn + wn + nt * 8 + 2 * t;
            float bi0 = bias[cc], bi1 = bias[cc + 1];
            float v00 = acc[mt][nt][0] + bi0, v01 = acc[mt][nt][1] + bi1;
            float v10 = acc[mt][nt][2] + bi0, v11 = acc[mt][nt][3] + bi1;
            if constexpr (sizeof(OutT) == 4) {
                *reinterpret_cast<float2*>(&C[(size_t)r * Nc + cc]) = make_float2(v00, v01);
                *reinterpret_cast<float2*>(&C[(size_t)(r + 8) * Nc + cc]) = make_float2(v10, v11);
            } else {
                __half2 h0 = __floats2half2_rn(v00, v01);
                __half2 h1 = __floats2half2_rn(v10, v11);
                *reinterpret_cast<__half2*>(&C[(size_t)r * Nc + cc])       = h0;
                *reinterpret_cast<__half2*>(&C[(size_t)(r + 8) * Nc + cc]) = h1;
            }
        }
    }
}

// ---------------- register-resident 6x6 attention ----------------
// One warp per (token, head). Lane l owns dims 2l, 2l+1 of the 64-dim head.
// No shared memory, no block syncs. grid = (NTOK, 2), block = 256 (8 warps).
__global__ __launch_bounds__(256)
void attn_reg_kernel(const __half* __restrict__ Q, const __half* __restrict__ Kb,
                     const __half* __restrict__ V, __half* __restrict__ CTX)
{
    const int n    = blockIdx.x;
    const int warp = threadIdx.x >> 5;
    const int lane = threadIdx.x & 31;
    const int h    = blockIdx.y * 8 + warp;
    const int col  = h * HDIM + 2 * lane;

    // load q, k (coalesced half2)
    float2 qf[NST], kf[NST];
    #pragma unroll
    for (int j = 0; j < NST; j++) {
        size_t base = ((size_t)j * NTOK + n) * EDIM + col;
        qf[j] = __half22float2(*reinterpret_cast<const __half2*>(Q + base));
        kf[j] = __half22float2(*reinterpret_cast<const __half2*>(Kb + base));
    }

    // per-lane score partials (2 dims each)
    float p[36];
    #pragma unroll
    for (int qi = 0; qi < NST; qi++)
        #pragma unroll
        for (int ki = 0; ki < NST; ki++)
            p[qi * 6 + ki] = qf[qi].x * kf[ki].x + qf[qi].y * kf[ki].y;

    // butterfly reduce across the warp -> every lane has full scores
    #pragma unroll
    for (int off = 16; off > 0; off >>= 1)
        #pragma unroll
        for (int i = 0; i < 36; i++)
            p[i] += __shfl_xor_sync(0xffffffffu, p[i], off);

    // softmax per q-row, in place (scale 1/sqrt(64) = 0.125)
    #pragma unroll
    for (int qi = 0; qi < NST; qi++) {
        float m = -1e30f;
        #pragma unroll
        for (int ki = 0; ki < NST; ki++) {
            p[qi * 6 + ki] *= 0.125f;
            m = fmaxf(m, p[qi * 6 + ki]);
        }
        float ssum = 0.f;
        #pragma unroll
        for (int ki = 0; ki < NST; ki++) {
            p[qi * 6 + ki] = __expf(p[qi * 6 + ki] - m);
            ssum += p[qi * 6 + ki];
        }
        float inv = 1.f / ssum;
        #pragma unroll
        for (int ki = 0; ki < NST; ki++) p[qi * 6 + ki] *= inv;
    }

    // load v AFTER softmax (caps live registers), compute ctx, store
    float2 vf[NST];
    #pragma unroll
    for (int j = 0; j < NST; j++) {
        size_t base = ((size_t)j * NTOK + n) * EDIM + col;
        vf[j] = __half22float2(*reinterpret_cast<const __half2*>(V + base));
    }
    #pragma unroll
    for (int qi = 0; qi < NST; qi++) {
        float cx = 0.f, cy = 0.f;
        #pragma unroll
        for (int ki = 0; ki < NST; ki++) {
            cx += p[qi * 6 + ki] * vf[ki].x;
            cy += p[qi * 6 + ki] * vf[ki].y;
        }
        size_t base = ((size_t)qi * NTOK + n) * EDIM + col;
        *reinterpret_cast<__half2*>(CTX + base) = __floats2half2_rn(cx, cy);
    }
}

// ---------------- block reduction helper (256 threads) ----------------
__device__ __forceinline__ float block_sum(float v, float* sbuf)
{
    const int lane = threadIdx.x & 31;
    const int wid  = threadIdx.x >> 5;
    #pragma unroll
    for (int o = 16; o > 0; o >>= 1) v += __shfl_xor_sync(0xffffffffu, v, o);
    if (lane == 0) sbuf[wid] = v;
    __syncthreads();
    if (wid == 0) {
        float r = (lane < 8) ? sbuf[lane] : 0.f;
        #pragma unroll
        for (int o = 4; o > 0; o >>= 1) r += __shfl_xor_sync(0xffffffffu, r, o);
        if (lane == 0) sbuf[0] = r;
    }
    __syncthreads();
    float r = sbuf[0];
    __syncthreads();
    return r;
}

// ---------------- residual + LN1 + softmax(fusion_w)-weighted sum (-> fp16) ----------------
__global__ __launch_bounds__(256)
void ln1_fuse_kernel(const float* __restrict__ ATT, const float* __restrict__ ST,
                     const float* __restrict__ g1, const float* __restrict__ b1,
                     const float* __restrict__ fw, __half* __restrict__ FUSED)
{
    __shared__ float sbuf[32];
    const int n = blockIdx.x, tid = threadIdx.x;

    float w[6];
    {
        float m = -1e30f;
        #pragma unroll
        for (int j = 0; j < 6; j++) { w[j] = fw[j]; m = fmaxf(m, w[j]); }
        float s = 0.f;
        #pragma unroll
        for (int j = 0; j < 6; j++) { w[j] = __expf(w[j] - m); s += w[j]; }
        float inv = 1.f / s;
        #pragma unroll
        for (int j = 0; j < 6; j++) w[j] *= inv;
    }

    float accv[4] = {0.f, 0.f, 0.f, 0.f};
    for (int j = 0; j < 6; j++) {
        size_t base = ((size_t)j * NTOK + n) * EDIM;
        float x[4], lsum = 0.f;
        #pragma unroll
        for (int tq = 0; tq < 4; tq++) {
            int e = tq * 256 + tid;
            x[tq] = ATT[base + e] + ST[base + e];
            lsum += x[tq];
        }
        float mean = block_sum(lsum, sbuf) * (1.f / EDIM);
        float lvar = 0.f;
        #pragma unroll
        for (int tq = 0; tq < 4; tq++) { float d = x[tq] - mean; lvar += d * d; }
        float var = block_sum(lvar, sbuf) * (1.f / EDIM);
        float inv = rsqrtf(var + LN_EPS);
        #pragma unroll
        for (int tq = 0; tq < 4; tq++) {
            int e = tq * 256 + tid;
            accv[tq] += w[j] * ((x[tq] - mean) * inv * g1[e] + b1[e]);
        }
    }
    #pragma unroll
    for (int tq = 0; tq < 4; tq++)
        FUSED[(size_t)n * EDIM + tq * 256 + tid] = __float2half_rn(accv[tq]);
}

// ---------------- LeakyReLU + LN2 (in-place on d_out) ----------------
__global__ __launch_bounds__(256)
void lrelu_ln2_kernel(float* __restrict__ O, const float* __restrict__ g2,
                      const float* __restrict__ b2)
{
    __shared__ float sbuf[32];
    const int n = blockIdx.x, tid = threadIdx.x;
    size_t base = (size_t)n * HIDD;

    float x[4], lsum = 0.f;
    #pragma unroll
    for (int tq = 0; tq < 4; tq++) {
        int e = tq * 256 + tid;
        float v = O[base + e];
        v = (v >= 0.f) ? v : 0.01f * v;
        x[tq] = v; lsum += v;
    }
    float mean = block_sum(lsum, sbuf) * (1.f / HIDD);
    float lvar = 0.f;
    #pragma unroll
    for (int tq = 0; tq < 4; tq++) { float d = x[tq] - mean; lvar += d * d; }
    float var = block_sum(lvar, sbuf) * (1.f / HIDD);
    float inv = rsqrtf(var + LN_EPS);
    #pragma unroll
    for (int tq = 0; tq < 4; tq++) {
        int e = tq * 256 + tid;
        O[base + e] = (x[tq] - mean) * inv * g2[e] + b2[e];
    }
}

// ---------------- launch ----------------
extern "C" void kernel_launch(void* const* d_in, const int* in_sizes, int n_in,
                              void* d_out, int out_size)
{
    const float* st = (const float*)d_in[0];
    const float* Wq = (const float*)d_in[1];  const float* bq = (const float*)d_in[2];
    const float* Wk = (const float*)d_in[3];  const float* bk = (const float*)d_in[4];
    const float* Wv = (const float*)d_in[5];  const float* bv = (const float*)d_in[6];
    const float* Wo = (const float*)d_in[7];  const float* bo = (const float*)d_in[8];
    const float* g1 = (const float*)d_in[9];  const float* b1 = (const float*)d_in[10];
    const float* fw = (const float*)d_in[11];
    const float* Wf = (const float*)d_in[12]; const float* bf = (const float*)d_in[13];
    const float* g2 = (const float*)d_in[14]; const float* b2 = (const float*)d_in[15];
    float* out = (float*)d_out;

    float *ATTb;
    __half *Qh, *Kh, *Vh, *STh, *CTXh, *FUSh, *Wqh, *Wkh, *Wvh, *Woh, *Wfh;
    cudaGetSymbolAddress((void**)&Qh,   g_Qh);
    cudaGetSymbolAddress((void**)&Kh,   g_Kh);
    cudaGetSymbolAddress((void**)&Vh,   g_Vh);
    cudaGetSymbolAddress((void**)&ATTb, g_ATT);
    cudaGetSymbolAddress((void**)&STh,  g_STh);
    cudaGetSymbolAddress((void**)&CTXh, g_CTXh);
    cudaGetSymbolAddress((void**)&FUSh, g_FUSEDh);
    cudaGetSymbolAddress((void**)&Wqh,  g_Wqh);
    cudaGetSymbolAddress((void**)&Wkh,  g_Wkh);
    cudaGetSymbolAddress((void**)&Wvh,  g_Wvh);
    cudaGetSymbolAddress((void**)&Woh,  g_Woh);
    cudaGetSymbolAddress((void**)&Wfh,  g_Wfh);

    cudaFuncSetAttribute(gemm_h<__half>, cudaFuncAttributeMaxDynamicSharedMemorySize,
                         GEMMH_SMEM);
    cudaFuncSetAttribute(gemm_h<float>, cudaFuncAttributeMaxDynamicSharedMemorySize,
                         GEMMH_SMEM);

    // ---- fp32 -> fp16 conversions ----
    {
        int n4 = (NROWS * EDIM) / 4;
        f2h_kernel<<<(n4 + 255) / 256, 256>>>((const float4*)st, (uint2*)STh, n4);
        int w4 = (EDIM * EDIM) / 4;
        f2h_kernel<<<(w4 + 255) / 256, 256>>>((const float4*)Wq, (uint2*)Wqh, w4);
        f2h_kernel<<<(w4 + 255) / 256, 256>>>((const float4*)Wk, (uint2*)Wkh, w4);
        f2h_kernel<<<(w4 + 255) / 256, 256>>>((const float4*)Wv, (uint2*)Wvh, w4);
        f2h_kernel<<<(w4 + 255) / 256, 256>>>((const float4*)Wo, (uint2*)Woh, w4);
        int f4 = (HIDD * EDIM) / 4;
        f2h_kernel<<<(f4 + 255) / 256, 256>>>((const float4*)Wf, (uint2*)Wfh, f4);
    }

    dim3 blk(256);
    dim3 gproj(EDIM / 128, NROWS / 128);   // (8, 384)
    gemm_h<__half><<<gproj, blk, GEMMH_SMEM>>>(STh, Wqh, bq, Qh, NROWS, EDIM, EDIM);
    gemm_h<__half><<<gproj, blk, GEMMH_SMEM>>>(STh, Wkh, bk, Kh, NROWS, EDIM, EDIM);
    gemm_h<__half><<<gproj, blk, GEMMH_SMEM>>>(STh, Wvh, bv, Vh, NROWS, EDIM, EDIM);

    attn_reg_kernel<<<dim3(NTOK, 2), 256>>>(Qh, Kh, Vh, CTXh);

    gemm_h<float><<<gproj, blk, GEMMH_SMEM>>>(CTXh, Woh, bo, ATTb, NROWS, EDIM, EDIM);

    ln1_fuse_kernel<<<NTOK, 256>>>(ATTb, st, g1, b1, fw, FUSh);

    dim3 gmlp(HIDD / 128, NTOK / 128);     // (8, 64)
    gemm_h<float><<<gmlp, blk, GEMMH_SMEM>>>(FUSh, Wfh, bf, out, NTOK, HIDD, EDIM);

    lrelu_ln2_kernel<<<NTOK, 256>>>(out, g2, b2);
}

// round 10
// speedup vs baseline: 1.7000x; 1.0827x over previous
#include <cuda_runtime.h>
#include <cuda_fp16.h>
#include <math.h>
#include <stdint.h>

// ---------------- problem constants ----------------
#define NTOK   8192          // B*S = 16*512
#define EDIM   1024
#define NHEAD  16
#define HDIM   64
#define NST    6
#define NROWS  (NST*NTOK)    // 49152
#define HIDD   1024
#define LN_EPS 1e-5f

// ---------------- scratch (device globals; no allocs allowed) ----------------
__device__ __half g_Qh[(size_t)NROWS * EDIM];
__device__ __half g_Kh[(size_t)NROWS * EDIM];
__device__ __half g_Vh[(size_t)NROWS * EDIM];
__device__ float  g_ATT[(size_t)NROWS * EDIM];
__device__ __half g_STh[(size_t)NROWS * EDIM];
__device__ __half g_CTXh[(size_t)NROWS * EDIM];
__device__ __half g_FUSEDh[(size_t)NTOK * EDIM];
__device__ __half g_Wqh[(size_t)EDIM * EDIM];
__device__ __half g_Wkh[(size_t)EDIM * EDIM];
__device__ __half g_Wvh[(size_t)EDIM * EDIM];
__device__ __half g_Woh[(size_t)EDIM * EDIM];
__device__ __half g_Wfh[(size_t)HIDD * EDIM];

// ---------------- helpers ----------------
__device__ __forceinline__ uint32_t smem_u32(const void* p) {
    uint32_t a;
    asm("{ .reg .u64 t; cvta.to.shared.u64 t, %1; cvt.u32.u64 %0, t; }" : "=r"(a) : "l"(p));
    return a;
}

__device__ __forceinline__ void cp_async16(uint32_t dst, const void* src) {
    asm volatile("cp.async.cg.shared.global [%0], [%1], 16;"
                 :: "r"(dst), "l"(src) : "memory");
}

__device__ __forceinline__ void ldsm_x4(uint32_t* r, uint32_t addr) {
    asm volatile("ldmatrix.sync.aligned.m8n8.x4.shared.b16 {%0,%1,%2,%3}, [%4];"
                 : "=r"(r[0]), "=r"(r[1]), "=r"(r[2]), "=r"(r[3]) : "r"(addr));
}

__device__ __forceinline__ void mma_fp16(float* c, const uint32_t* a, const uint32_t* b) {
    asm volatile(
        "mma.sync.aligned.m16n8k16.row.col.f32.f16.f16.f32 "
        "{%0,%1,%2,%3}, {%4,%5,%6,%7}, {%8,%9}, {%0,%1,%2,%3};"
        : "+f"(c[0]), "+f"(c[1]), "+f"(c[2]), "+f"(c[3])
        : "r"(a[0]), "r"(a[1]), "r"(a[2]), "r"(a[3]), "r"(b[0]), "r"(b[1]));
}

__device__ __forceinline__ uint32_t sw128(uint32_t byte) {
    return byte ^ ((byte >> 3) & 0x70);
}

// ---------------- fp32 -> fp16 conversion (vectorized) ----------------
__global__ __launch_bounds__(256)
void f2h_kernel(const float4* __restrict__ src, uint2* __restrict__ dst, int n4)
{
    int i = blockIdx.x * blockDim.x + threadIdx.x;
    if (i < n4) {
        float4 v = src[i];
        __half2 lo = __floats2half2_rn(v.x, v.y);
        __half2 hi = __floats2half2_rn(v.z, v.w);
        dst[i] = make_uint2(*reinterpret_cast<uint32_t*>(&lo),
                            *reinterpret_cast<uint32_t*>(&hi));
    }
}

// ---------------- FP16 tensor-core GEMM, fat-tile version ----------------
// C[M,Nc] = A[M,K] @ B[Nc,K]^T + bias[Nc], A/B fp16, OutT = fp32 or fp16.
// Block 256x128, BK=64 halves (128B rows, SW128), 256 threads = 8 warps (4x2),
// warp tile 64x64, 3-stage cp.async pipeline (one sync/stage), reg frag dbuf.
#define A_STG 32768                          // 256 rows * 128 B
#define B_STG 16384                          // 128 rows * 128 B
#define STG_TOT (A_STG + B_STG)              // 48 KB
#define NPIPE 3
#define GEMMH_SMEM (1024 + NPIPE * STG_TOT)  // 145.5 KB

extern __shared__ char dynsmem[];

template <typename OutT>
__global__ __launch_bounds__(256, 1)
void gemm_h(const __half* __restrict__ A, const __half* __restrict__ Bw,
            const float* __restrict__ bias, OutT* __restrict__ C,
            int M, int Nc, int Kd)
{
    const int tid  = threadIdx.x;
    const int warp = tid >> 5;
    const int lane = tid & 31;

    const int bm = blockIdx.y * 256;
    const int bn = blockIdx.x * 128;
    const int wm = (warp >> 1) * 64;     // 4 warp rows
    const int wn = (warp & 1) * 64;      // 2 warp cols

    uint32_t sbase = (smem_u32(dynsmem) + 1023u) & ~1023u;

    float acc[4][8][4];
    #pragma unroll
    for (int mt = 0; mt < 4; mt++)
        #pragma unroll
        for (int nt = 0; nt < 8; nt++)
            #pragma unroll
            for (int r = 0; r < 4; r++) acc[mt][nt][r] = 0.f;

    const int nstg = Kd / 64;

    const int a_row_in = lane & 15;
    const int a_ch     = lane >> 4;
    const int b_n_in = (lane & 7) + ((lane >> 4) & 1) * 8;
    const int b_ch   = (lane >> 3) & 1;

    auto load_stage = [&](int s, int buf) {
        const uint32_t da = sbase + buf * STG_TOT;          // A: 32KB
        const uint32_t db = da + A_STG;                     // B: 16KB
        #pragma unroll
        for (int i = 0; i < 8; i++) {                       // A: 2048 chunks
            int c = tid + i * 256;
            int row = c >> 3, col16 = c & 7;
            uint32_t sw = sw128(row * 128 + col16 * 16);
            cp_async16(da + sw, A + (size_t)(bm + row) * Kd + s * 64 + col16 * 8);
        }
        #pragma unroll
        for (int i = 0; i < 4; i++) {                       // B: 1024 chunks
            int c = tid + i * 256;
            int row = c >> 3, col16 = c & 7;
            uint32_t sw = sw128(row * 128 + col16 * 16);
            cp_async16(db + sw, Bw + (size_t)(bn + row) * Kd + s * 64 + col16 * 8);
        }
        asm volatile("cp.async.commit_group;" ::: "memory");
    };

    load_stage(0, 0);
    load_stage(1, 1);

    int buf = 0;
    for (int s = 0; s < nstg; s++) {
        asm volatile("cp.async.wait_group 1;" ::: "memory");
        __syncthreads();

        if (s + 2 < nstg) {
            int nb = buf + 2; if (nb >= NPIPE) nb -= NPIPE;
            load_stage(s + 2, nb);
        } else {
            asm volatile("cp.async.commit_group;" ::: "memory");
        }

        const uint32_t abuf = sbase + buf * STG_TOT;
        const uint32_t bbuf = abuf + A_STG;

        uint32_t af[2][4][4], bfg[2][4][4];
        // prefetch ks=0 fragments
        #pragma unroll
        for (int mt = 0; mt < 4; mt++) {
            uint32_t byte = (uint32_t)(wm + mt * 16 + a_row_in) * 128 + a_ch * 16;
            ldsm_x4(af[0][mt], abuf + sw128(byte));
        }
        #pragma unroll
        for (int nt2 = 0; nt2 < 4; nt2++) {
            uint32_t byte = (uint32_t)(wn + nt2 * 16 + b_n_in) * 128 + b_ch * 16;
            ldsm_x4(bfg[0][nt2], bbuf + sw128(byte));
        }

        #pragma unroll
        for (int ks = 0; ks < 4; ks++) {
            const int cur = ks & 1;
            if (ks < 3) {
                const int nxt = cur ^ 1;
                #pragma unroll
                for (int mt = 0; mt < 4; mt++) {
                    uint32_t byte = (uint32_t)(wm + mt * 16 + a_row_in) * 128
                                  + (ks + 1) * 32 + a_ch * 16;
                    ldsm_x4(af[nxt][mt], abuf + sw128(byte));
                }
                #pragma unroll
                for (int nt2 = 0; nt2 < 4; nt2++) {
                    uint32_t byte = (uint32_t)(wn + nt2 * 16 + b_n_in) * 128
                                  + (ks + 1) * 32 + b_ch * 16;
                    ldsm_x4(bfg[nxt][nt2], bbuf + sw128(byte));
                }
            }
            #pragma unroll
            for (int mt = 0; mt < 4; mt++)
                #pragma unroll
                for (int nt = 0; nt < 8; nt++)
                    mma_fp16(acc[mt][nt], af[cur][mt], &bfg[cur][nt >> 1][(nt & 1) * 2]);
        }

        buf++; if (buf == NPIPE) buf = 0;
    }

    // epilogue: bias + store
    const int g = lane >> 2;
    const int t = lane & 3;
    #pragma unroll
    for (int mt = 0; mt < 4; mt++) {
        int r = bm + wm + mt * 16 + g;
        #pragma unroll
        for (int nt = 0; nt < 8; nt++) {
            int cc = bn + wn + nt * 8 + 2 * t;
            float bi0 = bias[cc], bi1 = bias[cc + 1];
            float v00 = acc[mt][nt][0] + bi0, v01 = acc[mt][nt][1] + bi1;
            float v10 = acc[mt][nt][2] + bi0, v11 = acc[mt][nt][3] + bi1;
            if constexpr (sizeof(OutT) == 4) {
                *reinterpret_cast<float2*>(&C[(size_t)r * Nc + cc]) = make_float2(v00, v01);
                *reinterpret_cast<float2*>(&C[(size_t)(r + 8) * Nc + cc]) = make_float2(v10, v11);
            } else {
                __half2 h0 = __floats2half2_rn(v00, v01);
                __half2 h1 = __floats2half2_rn(v10, v11);
                *reinterpret_cast<__half2*>(&C[(size_t)r * Nc + cc])       = h0;
                *reinterpret_cast<__half2*>(&C[(size_t)(r + 8) * Nc + cc]) = h1;
            }
        }
    }
}

// ---------------- register-resident 6x6 attention ----------------
// One warp per (token, head). Lane l owns dims 2l, 2l+1 of the 64-dim head.
__global__ __launch_bounds__(256)
void attn_reg_kernel(const __half* __restrict__ Q, const __half* __restrict__ Kb,
                     const __half* __restrict__ V, __half* __restrict__ CTX)
{
    const int n    = blockIdx.x;
    const int warp = threadIdx.x >> 5;
    const int lane = threadIdx.x & 31;
    const int h    = blockIdx.y * 8 + warp;
    const int col  = h * HDIM + 2 * lane;

    float2 qf[NST], kf[NST];
    #pragma unroll
    for (int j = 0; j < NST; j++) {
        size_t base = ((size_t)j * NTOK + n) * EDIM + col;
        qf[j] = __half22float2(*reinterpret_cast<const __half2*>(Q + base));
        kf[j] = __half22float2(*reinterpret_cast<const __half2*>(Kb + base));
    }

    float p[36];
    #pragma unroll
    for (int qi = 0; qi < NST; qi++)
        #pragma unroll
        for (int ki = 0; ki < NST; ki++)
            p[qi * 6 + ki] = qf[qi].x * kf[ki].x + qf[qi].y * kf[ki].y;

    #pragma unroll
    for (int off = 16; off > 0; off >>= 1)
        #pragma unroll
        for (int i = 0; i < 36; i++)
            p[i] += __shfl_xor_sync(0xffffffffu, p[i], off);

    #pragma unroll
    for (int qi = 0; qi < NST; qi++) {
        float m = -1e30f;
        #pragma unroll
        for (int ki = 0; ki < NST; ki++) {
            p[qi * 6 + ki] *= 0.125f;
            m = fmaxf(m, p[qi * 6 + ki]);
        }
        float ssum = 0.f;
        #pragma unroll
        for (int ki = 0; ki < NST; ki++) {
            p[qi * 6 + ki] = __expf(p[qi * 6 + ki] - m);
            ssum += p[qi * 6 + ki];
        }
        float inv = 1.f / ssum;
        #pragma unroll
        for (int ki = 0; ki < NST; ki++) p[qi * 6 + ki] *= inv;
    }

    float2 vf[NST];
    #pragma unroll
    for (int j = 0; j < NST; j++) {
        size_t base = ((size_t)j * NTOK + n) * EDIM + col;
        vf[j] = __half22float2(*reinterpret_cast<const __half2*>(V + base));
    }
    #pragma unroll
    for (int qi = 0; qi < NST; qi++) {
        float cx = 0.f, cy = 0.f;
        #pragma unroll
        for (int ki = 0; ki < NST; ki++) {
            cx += p[qi * 6 + ki] * vf[ki].x;
            cy += p[qi * 6 + ki] * vf[ki].y;
        }
        size_t base = ((size_t)qi * NTOK + n) * EDIM + col;
        *reinterpret_cast<__half2*>(CTX + base) = __floats2half2_rn(cx, cy);
    }
}

// ---------------- block reduction helper (256 threads) ----------------
__device__ __forceinline__ float block_sum(float v, float* sbuf)
{
    const int lane = threadIdx.x & 31;
    const int wid  = threadIdx.x >> 5;
    #pragma unroll
    for (int o = 16; o > 0; o >>= 1) v += __shfl_xor_sync(0xffffffffu, v, o);
    if (lane == 0) sbuf[wid] = v;
    __syncthreads();
    if (wid == 0) {
        float r = (lane < 8) ? sbuf[lane] : 0.f;
        #pragma unroll
        for (int o = 4; o > 0; o >>= 1) r += __shfl_xor_sync(0xffffffffu, r, o);
        if (lane == 0) sbuf[0] = r;
    }
    __syncthreads();
    float r = sbuf[0];
    __syncthreads();
    return r;
}

// ---------------- residual + LN1 + softmax(fusion_w)-weighted sum (-> fp16) ----------------
__global__ __launch_bounds__(256)
void ln1_fuse_kernel(const float* __restrict__ ATT, const float* __restrict__ ST,
                     const float* __restrict__ g1, const float* __restrict__ b1,
                     const float* __restrict__ fw, __half* __restrict__ FUSED)
{
    __shared__ float sbuf[32];
    const int n = blockIdx.x, tid = threadIdx.x;

    float w[6];
    {
        float m = -1e30f;
        #pragma unroll
        for (int j = 0; j < 6; j++) { w[j] = fw[j]; m = fmaxf(m, w[j]); }
        float s = 0.f;
        #pragma unroll
        for (int j = 0; j < 6; j++) { w[j] = __expf(w[j] - m); s += w[j]; }
        float inv = 1.f / s;
        #pragma unroll
        for (int j = 0; j < 6; j++) w[j] *= inv;
    }

    float accv[4] = {0.f, 0.f, 0.f, 0.f};
    for (int j = 0; j < 6; j++) {
        size_t base = ((size_t)j * NTOK + n) * EDIM;
        float x[4], lsum = 0.f;
        #pragma unroll
        for (int tq = 0; tq < 4; tq++) {
            int e = tq * 256 + tid;
            x[tq] = ATT[base + e] + ST[base + e];
            lsum += x[tq];
        }
        float mean = block_sum(lsum, sbuf) * (1.f / EDIM);
        float lvar = 0.f;
        #pragma unroll
        for (int tq = 0; tq < 4; tq++) { float d = x[tq] - mean; lvar += d * d; }
        float var = block_sum(lvar, sbuf) * (1.f / EDIM);
        float inv = rsqrtf(var + LN_EPS);
        #pragma unroll
        for (int tq = 0; tq < 4; tq++) {
            int e = tq * 256 + tid;
            accv[tq] += w[j] * ((x[tq] - mean) * inv * g1[e] + b1[e]);
        }
    }
    #pragma unroll
    for (int tq = 0; tq < 4; tq++)
        FUSED[(size_t)n * EDIM + tq * 256 + tid] = __float2half_rn(accv[tq]);
}

// ---------------- LeakyReLU + LN2 (in-place on d_out) ----------------
__global__ __launch_bounds__(256)
void lrelu_ln2_kernel(float* __restrict__ O, const float* __restrict__ g2,
                      const float* __restrict__ b2)
{
    __shared__ float sbuf[32];
    const int n = blockIdx.x, tid = threadIdx.x;
    size_t base = (size_t)n * HIDD;

    float x[4], lsum = 0.f;
    #pragma unroll
    for (int tq = 0; tq < 4; tq++) {
        int e = tq * 256 + tid;
        float v = O[base + e];
        v = (v >= 0.f) ? v : 0.01f * v;
        x[tq] = v; lsum += v;
    }
    float mean = block_sum(lsum, sbuf) * (1.f / HIDD);
    float lvar = 0.f;
    #pragma unroll
    for (int tq = 0; tq < 4; tq++) { float d = x[tq] - mean; lvar += d * d; }
    float var = block_sum(lvar, sbuf) * (1.f / HIDD);
    float inv = rsqrtf(var + LN_EPS);
    #pragma unroll
    for (int tq = 0; tq < 4; tq++) {
        int e = tq * 256 + tid;
        O[base + e] = (x[tq] - mean) * inv * g2[e] + b2[e];
    }
}

// ---------------- launch ----------------
extern "C" void kernel_launch(void* const* d_in, const int* in_sizes, int n_in,
                              void* d_out, int out_size)
{
    const float* st = (const float*)d_in[0];
    const float* Wq = (const float*)d_in[1];  const float* bq = (const float*)d_in[2];
    const float* Wk = (const float*)d_in[3];  const float* bk = (const float*)d_in[4];
    const float* Wv = (const float*)d_in[5];  const float* bv = (const float*)d_in[6];
    const float* Wo = (const float*)d_in[7];  const float* bo = (const float*)d_in[8];
    const float* g1 = (const float*)d_in[9];  const float* b1 = (const float*)d_in[10];
    const float* fw = (const float*)d_in[11];
    const float* Wf = (const float*)d_in[12]; const float* bf = (const float*)d_in[13];
    const float* g2 = (const float*)d_in[14]; const float* b2 = (const float*)d_in[15];
    float* out = (float*)d_out;

    float *ATTb;
    __half *Qh, *Kh, *Vh, *STh, *CTXh, *FUSh, *Wqh, *Wkh, *Wvh, *Woh, *Wfh;
    cudaGetSymbolAddress((void**)&Qh,   g_Qh);
    cudaGetSymbolAddress((void**)&Kh,   g_Kh);
    cudaGetSymbolAddress((void**)&Vh,   g_Vh);
    cudaGetSymbolAddress((void**)&ATTb, g_ATT);
    cudaGetSymbolAddress((void**)&STh,  g_STh);
    cudaGetSymbolAddress((void**)&CTXh, g_CTXh);
    cudaGetSymbolAddress((void**)&FUSh, g_FUSEDh);
    cudaGetSymbolAddress((void**)&Wqh,  g_Wqh);
    cudaGetSymbolAddress((void**)&Wkh,  g_Wkh);
    cudaGetSymbolAddress((void**)&Wvh,  g_Wvh);
    cudaGetSymbolAddress((void**)&Woh,  g_Woh);
    cudaGetSymbolAddress((void**)&Wfh,  g_Wfh);

    cudaFuncSetAttribute(gemm_h<__half>, cudaFuncAttributeMaxDynamicSharedMemorySize,
                         GEMMH_SMEM);
    cudaFuncSetAttribute(gemm_h<float>, cudaFuncAttributeMaxDynamicSharedMemorySize,
                         GEMMH_SMEM);

    // ---- fp32 -> fp16 conversions ----
    {
        int n4 = (NROWS * EDIM) / 4;
        f2h_kernel<<<(n4 + 255) / 256, 256>>>((const float4*)st, (uint2*)STh, n4);
        int w4 = (EDIM * EDIM) / 4;
        f2h_kernel<<<(w4 + 255) / 256, 256>>>((const float4*)Wq, (uint2*)Wqh, w4);
        f2h_kernel<<<(w4 + 255) / 256, 256>>>((const float4*)Wk, (uint2*)Wkh, w4);
        f2h_kernel<<<(w4 + 255) / 256, 256>>>((const float4*)Wv, (uint2*)Wvh, w4);
        f2h_kernel<<<(w4 + 255) / 256, 256>>>((const float4*)Wo, (uint2*)Woh, w4);
        int f4 = (HIDD * EDIM) / 4;
        f2h_kernel<<<(f4 + 255) / 256, 256>>>((const float4*)Wf, (uint2*)Wfh, f4);
    }

    dim3 blk(256);
    dim3 gproj(EDIM / 128, NROWS / 256);   // (8, 192)
    gemm_h<__half><<<gproj, blk, GEMMH_SMEM>>>(STh, Wqh, bq, Qh, NROWS, EDIM, EDIM);
    gemm_h<__half><<<gproj, blk, GEMMH_SMEM>>>(STh, Wkh, bk, Kh, NROWS, EDIM, EDIM);
    gemm_h<__half><<<gproj, blk, GEMMH_SMEM>>>(STh, Wvh, bv, Vh, NROWS, EDIM, EDIM);

    attn_reg_kernel<<<dim3(NTOK, 2), 256>>>(Qh, Kh, Vh, CTXh);

    gemm_h<float><<<gproj, blk, GEMMH_SMEM>>>(CTXh, Woh, bo, ATTb, NROWS, EDIM, EDIM);

    ln1_fuse_kernel<<<NTOK, 256>>>(ATTb, st, g1, b1, fw, FUSh);

    dim3 gmlp(HIDD / 128, NTOK / 256);     // (8, 32)
    gemm_h<float><<<gmlp, blk, GEMMH_SMEM>>>(FUSh, Wfh, bf, out, NTOK, HIDD, EDIM);

    lrelu_ln2_kernel<<<NTOK, 256>>>(out, g2, b2);
}

// round 11
// speedup vs baseline: 1.7265x; 1.0155x over previous
#include <cuda_runtime.h>
#include <cuda_fp16.h>
#include <math.h>
#include <stdint.h>

// ---------------- problem constants ----------------
#define NTOK   8192          // B*S = 16*512
#define EDIM   1024
#define NHEAD  16
#define HDIM   64
#define NST    6
#define NROWS  (NST*NTOK)    // 49152
#define HIDD   1024
#define LN_EPS 1e-5f

// ---------------- scratch (device globals; no allocs allowed) ----------------
__device__ __half g_Qh[(size_t)NROWS * EDIM];
__device__ __half g_Kh[(size_t)NROWS * EDIM];
__device__ __half g_Vh[(size_t)NROWS * EDIM];
__device__ __half g_ATTh[(size_t)NROWS * EDIM];
__device__ __half g_STh[(size_t)NROWS * EDIM];
__device__ __half g_CTXh[(size_t)NROWS * EDIM];
__device__ __half g_FUSEDh[(size_t)NTOK * EDIM];
__device__ __half g_Wqh[(size_t)EDIM * EDIM];
__device__ __half g_Wkh[(size_t)EDIM * EDIM];
__device__ __half g_Wvh[(size_t)EDIM * EDIM];
__device__ __half g_Woh[(size_t)EDIM * EDIM];
__device__ __half g_Wfh[(size_t)HIDD * EDIM];

// ---------------- helpers ----------------
__device__ __forceinline__ uint32_t smem_u32(const void* p) {
    uint32_t a;
    asm("{ .reg .u64 t; cvta.to.shared.u64 t, %1; cvt.u32.u64 %0, t; }" : "=r"(a) : "l"(p));
    return a;
}

__device__ __forceinline__ void cp_async16(uint32_t dst, const void* src) {
    asm volatile("cp.async.cg.shared.global [%0], [%1], 16;"
                 :: "r"(dst), "l"(src) : "memory");
}

__device__ __forceinline__ void ldsm_x4(uint32_t* r, uint32_t addr) {
    asm volatile("ldmatrix.sync.aligned.m8n8.x4.shared.b16 {%0,%1,%2,%3}, [%4];"
                 : "=r"(r[0]), "=r"(r[1]), "=r"(r[2]), "=r"(r[3]) : "r"(addr));
}

__device__ __forceinline__ void mma_fp16(float* c, const uint32_t* a, const uint32_t* b) {
    asm volatile(
        "mma.sync.aligned.m16n8k16.row.col.f32.f16.f16.f32 "
        "{%0,%1,%2,%3}, {%4,%5,%6,%7}, {%8,%9}, {%0,%1,%2,%3};"
        : "+f"(c[0]), "+f"(c[1]), "+f"(c[2]), "+f"(c[3])
        : "r"(a[0]), "r"(a[1]), "r"(a[2]), "r"(a[3]), "r"(b[0]), "r"(b[1]));
}

__device__ __forceinline__ uint32_t sw128(uint32_t byte) {
    return byte ^ ((byte >> 3) & 0x70);
}

// ---------------- fp32 -> fp16 conversion (vectorized) ----------------
__global__ __launch_bounds__(256)
void f2h_kernel(const float4* __restrict__ src, uint2* __restrict__ dst, int n4)
{
    int i = blockIdx.x * blockDim.x + threadIdx.x;
    if (i < n4) {
        float4 v = src[i];
        __half2 lo = __floats2half2_rn(v.x, v.y);
        __half2 hi = __floats2half2_rn(v.z, v.w);
        dst[i] = make_uint2(*reinterpret_cast<uint32_t*>(&lo),
                            *reinterpret_cast<uint32_t*>(&hi));
    }
}

// ---------------- FP16 tensor-core GEMM, fat-tile version ----------------
// C[M,Nc] = A[M,K] @ B[Nc,K]^T + bias[Nc], A/B fp16, OutT = fp32 or fp16.
// Block 256x128, BK=64 halves (128B rows, SW128), 256 threads = 8 warps (4x2),
// warp tile 64x64, 3-stage cp.async pipeline (one sync/stage), reg frag dbuf.
#define A_STG 32768                          // 256 rows * 128 B
#define B_STG 16384                          // 128 rows * 128 B
#define STG_TOT (A_STG + B_STG)              // 48 KB
#define NPIPE 3
#define GEMMH_SMEM (1024 + NPIPE * STG_TOT)  // 145.5 KB

extern __shared__ char dynsmem[];

template <typename OutT>
__global__ __launch_bounds__(256, 1)
void gemm_h(const __half* __restrict__ A, const __half* __restrict__ Bw,
            const float* __restrict__ bias, OutT* __restrict__ C,
            int M, int Nc, int Kd)
{
    const int tid  = threadIdx.x;
    const int warp = tid >> 5;
    const int lane = tid & 31;

    const int bm = blockIdx.y * 256;
    const int bn = blockIdx.x * 128;
    const int wm = (warp >> 1) * 64;     // 4 warp rows
    const int wn = (warp & 1) * 64;      // 2 warp cols

    uint32_t sbase = (smem_u32(dynsmem) + 1023u) & ~1023u;

    float acc[4][8][4];
    #pragma unroll
    for (int mt = 0; mt < 4; mt++)
        #pragma unroll
        for (int nt = 0; nt < 8; nt++)
            #pragma unroll
            for (int r = 0; r < 4; r++) acc[mt][nt][r] = 0.f;

    const int nstg = Kd / 64;

    const int a_row_in = lane & 15;
    const int a_ch     = lane >> 4;
    const int b_n_in = (lane & 7) + ((lane >> 4) & 1) * 8;
    const int b_ch   = (lane >> 3) & 1;

    auto load_stage = [&](int s, int buf) {
        const uint32_t da = sbase + buf * STG_TOT;          // A: 32KB
        const uint32_t db = da + A_STG;                     // B: 16KB
        #pragma unroll
        for (int i = 0; i < 8; i++) {                       // A: 2048 chunks
            int c = tid + i * 256;
            int row = c >> 3, col16 = c & 7;
            uint32_t sw = sw128(row * 128 + col16 * 16);
            cp_async16(da + sw, A + (size_t)(bm + row) * Kd + s * 64 + col16 * 8);
        }
        #pragma unroll
        for (int i = 0; i < 4; i++) {                       // B: 1024 chunks
            int c = tid + i * 256;
            int row = c >> 3, col16 = c & 7;
            uint32_t sw = sw128(row * 128 + col16 * 16);
            cp_async16(db + sw, Bw + (size_t)(bn + row) * Kd + s * 64 + col16 * 8);
        }
        asm volatile("cp.async.commit_group;" ::: "memory");
    };

    load_stage(0, 0);
    load_stage(1, 1);

    int buf = 0;
    for (int s = 0; s < nstg; s++) {
        asm volatile("cp.async.wait_group 1;" ::: "memory");
        __syncthreads();

        if (s + 2 < nstg) {
            int nb = buf + 2; if (nb >= NPIPE) nb -= NPIPE;
            load_stage(s + 2, nb);
        } else {
            asm volatile("cp.async.commit_group;" ::: "memory");
        }

        const uint32_t abuf = sbase + buf * STG_TOT;
        const uint32_t bbuf = abuf + A_STG;

        uint32_t af[2][4][4], bfg[2][4][4];
        // prefetch ks=0 fragments
        #pragma unroll
        for (int mt = 0; mt < 4; mt++) {
            uint32_t byte = (uint32_t)(wm + mt * 16 + a_row_in) * 128 + a_ch * 16;
            ldsm_x4(af[0][mt], abuf + sw128(byte));
        }
        #pragma unroll
        for (int nt2 = 0; nt2 < 4; nt2++) {
            uint32_t byte = (uint32_t)(wn + nt2 * 16 + b_n_in) * 128 + b_ch * 16;
            ldsm_x4(bfg[0][nt2], bbuf + sw128(byte));
        }

        #pragma unroll
        for (int ks = 0; ks < 4; ks++) {
            const int cur = ks & 1;
            if (ks < 3) {
                const int nxt = cur ^ 1;
                #pragma unroll
                for (int mt = 0; mt < 4; mt++) {
                    uint32_t byte = (uint32_t)(wm + mt * 16 + a_row_in) * 128
                                  + (ks + 1) * 32 + a_ch * 16;
                    ldsm_x4(af[nxt][mt], abuf + sw128(byte));
                }
                #pragma unroll
                for (int nt2 = 0; nt2 < 4; nt2++) {
                    uint32_t byte = (uint32_t)(wn + nt2 * 16 + b_n_in) * 128
                                  + (ks + 1) * 32 + b_ch * 16;
                    ldsm_x4(bfg[nxt][nt2], bbuf + sw128(byte));
                }
            }
            #pragma unroll
            for (int mt = 0; mt < 4; mt++)
                #pragma unroll
                for (int nt = 0; nt < 8; nt++)
                    mma_fp16(acc[mt][nt], af[cur][mt], &bfg[cur][nt >> 1][(nt & 1) * 2]);
        }

        buf++; if (buf == NPIPE) buf = 0;
    }

    // epilogue: bias + store
    const int g = lane >> 2;
    const int t = lane & 3;
    #pragma unroll
    for (int mt = 0; mt < 4; mt++) {
        int r = bm + wm + mt * 16 + g;
        #pragma unroll
        for (int nt = 0; nt < 8; nt++) {
            int cc = bn + wn + nt * 8 + 2 * t;
            float bi0 = bias[cc], bi1 = bias[cc + 1];
            float v00 = acc[mt][nt][0] + bi0, v01 = acc[mt][nt][1] + bi1;
            float v10 = acc[mt][nt][2] + bi0, v11 = acc[mt][nt][3] + bi1;
            if constexpr (sizeof(OutT) == 4) {
                *reinterpret_cast<float2*>(&C[(size_t)r * Nc + cc]) = make_float2(v00, v01);
                *reinterpret_cast<float2*>(&C[(size_t)(r + 8) * Nc + cc]) = make_float2(v10, v11);
            } else {
                __half2 h0 = __floats2half2_rn(v00, v01);
                __half2 h1 = __floats2half2_rn(v10, v11);
                *reinterpret_cast<__half2*>(&C[(size_t)r * Nc + cc])       = h0;
                *reinterpret_cast<__half2*>(&C[(size_t)(r + 8) * Nc + cc]) = h1;
            }
        }
    }
}

// ---------------- register-resident 6x6 attention ----------------
// One warp per (token, head). Lane l owns dims 2l, 2l+1 of the 64-dim head.
__global__ __launch_bounds__(256)
void attn_reg_kernel(const __half* __restrict__ Q, const __half* __restrict__ Kb,
                     const __half* __restrict__ V, __half* __restrict__ CTX)
{
    const int n    = blockIdx.x;
    const int warp = threadIdx.x >> 5;
    const int lane = threadIdx.x & 31;
    const int h    = blockIdx.y * 8 + warp;
    const int col  = h * HDIM + 2 * lane;

    float2 qf[NST], kf[NST];
    #pragma unroll
    for (int j = 0; j < NST; j++) {
        size_t base = ((size_t)j * NTOK + n) * EDIM + col;
        qf[j] = __half22float2(*reinterpret_cast<const __half2*>(Q + base));
        kf[j] = __half22float2(*reinterpret_cast<const __half2*>(Kb + base));
    }

    float p[36];
    #pragma unroll
    for (int qi = 0; qi < NST; qi++)
        #pragma unroll
        for (int ki = 0; ki < NST; ki++)
            p[qi * 6 + ki] = qf[qi].x * kf[ki].x + qf[qi].y * kf[ki].y;

    #pragma unroll
    for (int off = 16; off > 0; off >>= 1)
        #pragma unroll
        for (int i = 0; i < 36; i++)
            p[i] += __shfl_xor_sync(0xffffffffu, p[i], off);

    #pragma unroll
    for (int qi = 0; qi < NST; qi++) {
        float m = -1e30f;
        #pragma unroll
        for (int ki = 0; ki < NST; ki++) {
            p[qi * 6 + ki] *= 0.125f;
            m = fmaxf(m, p[qi * 6 + ki]);
        }
        float ssum = 0.f;
        #pragma unroll
        for (int ki = 0; ki < NST; ki++) {
            p[qi * 6 + ki] = __expf(p[qi * 6 + ki] - m);
            ssum += p[qi * 6 + ki];
        }
        float inv = 1.f / ssum;
        #pragma unroll
        for (int ki = 0; ki < NST; ki++) p[qi * 6 + ki] *= inv;
    }

    float2 vf[NST];
    #pragma unroll
    for (int j = 0; j < NST; j++) {
        size_t base = ((size_t)j * NTOK + n) * EDIM + col;
        vf[j] = __half22float2(*reinterpret_cast<const __half2*>(V + base));
    }
    #pragma unroll
    for (int qi = 0; qi < NST; qi++) {
        float cx = 0.f, cy = 0.f;
        #pragma unroll
        for (int ki = 0; ki < NST; ki++) {
            cx += p[qi * 6 + ki] * vf[ki].x;
            cy += p[qi * 6 + ki] * vf[ki].y;
        }
        size_t base = ((size_t)qi * NTOK + n) * EDIM + col;
        *reinterpret_cast<__half2*>(CTX + base) = __floats2half2_rn(cx, cy);
    }
}

// ---------------- block reduction helper (256 threads) ----------------
__device__ __forceinline__ float block_sum(float v, float* sbuf)
{
    const int lane = threadIdx.x & 31;
    const int wid  = threadIdx.x >> 5;
    #pragma unroll
    for (int o = 16; o > 0; o >>= 1) v += __shfl_xor_sync(0xffffffffu, v, o);
    if (lane == 0) sbuf[wid] = v;
    __syncthreads();
    if (wid == 0) {
        float r = (lane < 8) ? sbuf[lane] : 0.f;
        #pragma unroll
        for (int o = 4; o > 0; o >>= 1) r += __shfl_xor_sync(0xffffffffu, r, o);
        if (lane == 0) sbuf[0] = r;
    }
    __syncthreads();
    float r = sbuf[0];
    __syncthreads();
    return r;
}

// ---------------- residual + LN1 + softmax(fusion_w)-weighted sum ----------------
// fp16 inputs (ATT, ST), fp32 math, fp16 output. half2 vector loads.
__global__ __launch_bounds__(256)
void ln1_fuse_kernel(const __half* __restrict__ ATT, const __half* __restrict__ ST,
                     const float* __restrict__ g1, const float* __restrict__ b1,
                     const float* __restrict__ fw, __half* __restrict__ FUSED)
{
    __shared__ float sbuf[32];
    const int n = blockIdx.x, tid = threadIdx.x;
    const __half2* A2 = reinterpret_cast<const __half2*>(ATT);
    const __half2* S2 = reinterpret_cast<const __half2*>(ST);
    __half2* F2 = reinterpret_cast<__half2*>(FUSED);

    float w[6];
    {
        float m = -1e30f;
        #pragma unroll
        for (int j = 0; j < 6; j++) { w[j] = fw[j]; m = fmaxf(m, w[j]); }
        float s = 0.f;
        #pragma unroll
        for (int j = 0; j < 6; j++) { w[j] = __expf(w[j] - m); s += w[j]; }
        float inv = 1.f / s;
        #pragma unroll
        for (int j = 0; j < 6; j++) w[j] *= inv;
    }

    // element indices: pair0 = 2*tid, 2*tid+1 ; pair1 = 2*(tid+256), +1
    const int e00 = 2 * tid,        e01 = e00 + 1;
    const int e10 = 2 * (tid + 256), e11 = e10 + 1;
    const float g1v[4] = { g1[e00], g1[e01], g1[e10], g1[e11] };
    const float b1v[4] = { b1[e00], b1[e01], b1[e10], b1[e11] };

    float accv[4] = {0.f, 0.f, 0.f, 0.f};
    for (int j = 0; j < 6; j++) {
        size_t b2 = ((size_t)j * NTOK + n) * (EDIM / 2);
        float2 a0 = __half22float2(A2[b2 + tid]);
        float2 a1 = __half22float2(A2[b2 + 256 + tid]);
        float2 s0 = __half22float2(S2[b2 + tid]);
        float2 s1 = __half22float2(S2[b2 + 256 + tid]);
        float x[4];
        x[0] = a0.x + s0.x; x[1] = a0.y + s0.y;
        x[2] = a1.x + s1.x; x[3] = a1.y + s1.y;
        float lsum = x[0] + x[1] + x[2] + x[3];
        float mean = block_sum(lsum, sbuf) * (1.f / EDIM);
        float lvar = 0.f;
        #pragma unroll
        for (int tq = 0; tq < 4; tq++) { float d = x[tq] - mean; lvar += d * d; }
        float var = block_sum(lvar, sbuf) * (1.f / EDIM);
        float inv = rsqrtf(var + LN_EPS);
        #pragma unroll
        for (int tq = 0; tq < 4; tq++)
            accv[tq] += w[j] * ((x[tq] - mean) * inv * g1v[tq] + b1v[tq]);
    }
    F2[(size_t)n * (EDIM / 2) + tid]       = __floats2half2_rn(accv[0], accv[1]);
    F2[(size_t)n * (EDIM / 2) + 256 + tid] = __floats2half2_rn(accv[2], accv[3]);
}

// ---------------- LeakyReLU + LN2 (in-place on d_out) ----------------
__global__ __launch_bounds__(256)
void lrelu_ln2_kernel(float* __restrict__ O, const float* __restrict__ g2,
                      const float* __restrict__ b2)
{
    __shared__ float sbuf[32];
    const int n = blockIdx.x, tid = threadIdx.x;
    size_t base = (size_t)n * HIDD;

    float x[4], lsum = 0.f;
    #pragma unroll
    for (int tq = 0; tq < 4; tq++) {
        int e = tq * 256 + tid;
        float v = O[base + e];
        v = (v >= 0.f) ? v : 0.01f * v;
        x[tq] = v; lsum += v;
    }
    float mean = block_sum(lsum, sbuf) * (1.f / HIDD);
    float lvar = 0.f;
    #pragma unroll
    for (int tq = 0; tq < 4; tq++) { float d = x[tq] - mean; lvar += d * d; }
    float var = block_sum(lvar, sbuf) * (1.f / HIDD);
    float inv = rsqrtf(var + LN_EPS);
    #pragma unroll
    for (int tq = 0; tq < 4; tq++) {
        int e = tq * 256 + tid;
        O[base + e] = (x[tq] - mean) * inv * g2[e] + b2[e];
    }
}

// ---------------- launch ----------------
extern "C" void kernel_launch(void* const* d_in, const int* in_sizes, int n_in,
                              void* d_out, int out_size)
{
    const float* st = (const float*)d_in[0];
    const float* Wq = (const float*)d_in[1];  const float* bq = (const float*)d_in[2];
    const float* Wk = (const float*)d_in[3];  const float* bk = (const float*)d_in[4];
    const float* Wv = (const float*)d_in[5];  const float* bv = (const float*)d_in[6];
    const float* Wo = (const float*)d_in[7];  const float* bo = (const float*)d_in[8];
    const float* g1 = (const float*)d_in[9];  const float* b1 = (const float*)d_in[10];
    const float* fw = (const float*)d_in[11];
    const float* Wf = (const float*)d_in[12]; const float* bf = (const float*)d_in[13];
    const float* g2 = (const float*)d_in[14]; const float* b2 = (const float*)d_in[15];
    float* out = (float*)d_out;

    __half *Qh, *Kh, *Vh, *ATTh, *STh, *CTXh, *FUSh, *Wqh, *Wkh, *Wvh, *Woh, *Wfh;
    cudaGetSymbolAddress((void**)&Qh,   g_Qh);
    cudaGetSymbolAddress((void**)&Kh,   g_Kh);
    cudaGetSymbolAddress((void**)&Vh,   g_Vh);
    cudaGetSymbolAddress((void**)&ATTh, g_ATTh);
    cudaGetSymbolAddress((void**)&STh,  g_STh);
    cudaGetSymbolAddress((void**)&CTXh, g_CTXh);
    cudaGetSymbolAddress((void**)&FUSh, g_FUSEDh);
    cudaGetSymbolAddress((void**)&Wqh,  g_Wqh);
    cudaGetSymbolAddress((void**)&Wkh,  g_Wkh);
    cudaGetSymbolAddress((void**)&Wvh,  g_Wvh);
    cudaGetSymbolAddress((void**)&Woh,  g_Woh);
    cudaGetSymbolAddress((void**)&Wfh,  g_Wfh);

    cudaFuncSetAttribute(gemm_h<__half>, cudaFuncAttributeMaxDynamicSharedMemorySize,
                         GEMMH_SMEM);
    cudaFuncSetAttribute(gemm_h<float>, cudaFuncAttributeMaxDynamicSharedMemorySize,
                         GEMMH_SMEM);

    // ---- fp32 -> fp16 conversions ----
    {
        int n4 = (NROWS * EDIM) / 4;
        f2h_kernel<<<(n4 + 255) / 256, 256>>>((const float4*)st, (uint2*)STh, n4);
        int w4 = (EDIM * EDIM) / 4;
        f2h_kernel<<<(w4 + 255) / 256, 256>>>((const float4*)Wq, (uint2*)Wqh, w4);
        f2h_kernel<<<(w4 + 255) / 256, 256>>>((const float4*)Wk, (uint2*)Wkh, w4);
        f2h_kernel<<<(w4 + 255) / 256, 256>>>((const float4*)Wv, (uint2*)Wvh, w4);
        f2h_kernel<<<(w4 + 255) / 256, 256>>>((const float4*)Wo, (uint2*)Woh, w4);
        int f4 = (HIDD * EDIM) / 4;
        f2h_kernel<<<(f4 + 255) / 256, 256>>>((const float4*)Wf, (uint2*)Wfh, f4);
    }

    dim3 blk(256);
    dim3 gproj(EDIM / 128, NROWS / 256);   // (8, 192)
    gemm_h<__half><<<gproj, blk, GEMMH_SMEM>>>(STh, Wqh, bq, Qh, NROWS, EDIM, EDIM);
    gemm_h<__half><<<gproj, blk, GEMMH_SMEM>>>(STh, Wkh, bk, Kh, NROWS, EDIM, EDIM);
    gemm_h<__half><<<gproj, blk, GEMMH_SMEM>>>(STh, Wvh, bv, Vh, NROWS, EDIM, EDIM);

    attn_reg_kernel<<<dim3(NTOK, 2), 256>>>(Qh, Kh, Vh, CTXh);

    gemm_h<__half><<<gproj, blk, GEMMH_SMEM>>>(CTXh, Woh, bo, ATTh, NROWS, EDIM, EDIM);

    ln1_fuse_kernel<<<NTOK, 256>>>(ATTh, STh, g1, b1, fw, FUSh);

    dim3 gmlp(HIDD / 128, NTOK / 256);     // (8, 32)
    gemm_h<float><<<gmlp, blk, GEMMH_SMEM>>>(FUSh, Wfh, bf, out, NTOK, HIDD, EDIM);

    lrelu_ln2_kernel<<<NTOK, 256>>>(out, g2, b2);
}

// round 12
// speedup vs baseline: 1.7943x; 1.0393x over previous
#include <cuda_runtime.h>
#include <cuda_fp16.h>
#include <math.h>
#include <stdint.h>

// ---------------- problem constants ----------------
#define NTOK   8192          // B*S = 16*512
#define EDIM   1024
#define NHEAD  16
#define HDIM   64
#define NST    6
#define NROWS  (NST*NTOK)    // 49152
#define HIDD   1024
#define LN_EPS 1e-5f

// ---------------- scratch (device globals; no allocs allowed) ----------------
__device__ __half g_Qh[(size_t)NROWS * EDIM];
__device__ __half g_Kh[(size_t)NROWS * EDIM];
__device__ __half g_Vh[(size_t)NROWS * EDIM];
__device__ __half g_ATTh[(size_t)NROWS * EDIM];
__device__ __half g_STh[(size_t)NROWS * EDIM];
__device__ __half g_CTXh[(size_t)NROWS * EDIM];
__device__ __half g_FUSEDh[(size_t)NTOK * EDIM];
__device__ __half g_Wqh[(size_t)EDIM * EDIM];
__device__ __half g_Wkh[(size_t)EDIM * EDIM];
__device__ __half g_Wvh[(size_t)EDIM * EDIM];
__device__ __half g_Woh[(size_t)EDIM * EDIM];
__device__ __half g_Wfh[(size_t)HIDD * EDIM];

// ---------------- helpers ----------------
__device__ __forceinline__ uint32_t smem_u32(const void* p) {
    uint32_t a;
    asm("{ .reg .u64 t; cvta.to.shared.u64 t, %1; cvt.u32.u64 %0, t; }" : "=r"(a) : "l"(p));
    return a;
}

__device__ __forceinline__ void cp_async16(uint32_t dst, const void* src) {
    asm volatile("cp.async.cg.shared.global [%0], [%1], 16;"
                 :: "r"(dst), "l"(src) : "memory");
}

__device__ __forceinline__ void ldsm_x4(uint32_t* r, uint32_t addr) {
    asm volatile("ldmatrix.sync.aligned.m8n8.x4.shared.b16 {%0,%1,%2,%3}, [%4];"
                 : "=r"(r[0]), "=r"(r[1]), "=r"(r[2]), "=r"(r[3]) : "r"(addr));
}

__device__ __forceinline__ void mma_fp16(float* c, const uint32_t* a, const uint32_t* b) {
    asm volatile(
        "mma.sync.aligned.m16n8k16.row.col.f32.f16.f16.f32 "
        "{%0,%1,%2,%3}, {%4,%5,%6,%7}, {%8,%9}, {%0,%1,%2,%3};"
        : "+f"(c[0]), "+f"(c[1]), "+f"(c[2]), "+f"(c[3])
        : "r"(a[0]), "r"(a[1]), "r"(a[2]), "r"(a[3]), "r"(b[0]), "r"(b[1]));
}

__device__ __forceinline__ uint32_t sw128(uint32_t byte) {
    return byte ^ ((byte >> 3) & 0x70);
}

// ---------------- fused fp32 -> fp16 conversion (segmented) ----------------
struct F2HSeg { const float4* src; uint2* dst; unsigned end; };
struct F2HBatch { F2HSeg seg[6]; };

__global__ __launch_bounds__(256)
void f2h_multi(F2HBatch b, unsigned total)
{
    unsigned i = blockIdx.x * 256u + threadIdx.x;
    if (i >= total) return;
    unsigned prev = 0;
    #pragma unroll
    for (int s = 0; s < 6; s++) {
        if (i < b.seg[s].end) {
            unsigned off = i - prev;
            float4 v = b.seg[s].src[off];
            __half2 lo = __floats2half2_rn(v.x, v.y);
            __half2 hi = __floats2half2_rn(v.z, v.w);
            b.seg[s].dst[off] = make_uint2(*reinterpret_cast<uint32_t*>(&lo),
                                           *reinterpret_cast<uint32_t*>(&hi));
            return;
        }
        prev = b.seg[s].end;
    }
}

// ---------------- FP16 tensor-core GEMM body (fat tile) ----------------
// C[.,Nc] tile at (bm,bn): A[M,K] @ B[Nc,K]^T + bias, optional fp16 residual.
// Block 256x128, BK=64 halves (128B rows, SW128), 256 threads = 8 warps (4x2),
// warp tile 64x64, 3-stage cp.async pipeline, reg frag dbuf.
#define A_STG 32768                          // 256 rows * 128 B
#define B_STG 16384                          // 128 rows * 128 B
#define STG_TOT (A_STG + B_STG)              // 48 KB
#define NPIPE 3
#define GEMMH_SMEM (1024 + NPIPE * STG_TOT)  // 145.5 KB

extern __shared__ char dynsmem[];

template <typename OutT>
__device__ __forceinline__
void gemm_body(const __half* __restrict__ A, const __half* __restrict__ Bw,
               const float* __restrict__ bias, OutT* __restrict__ C,
               const __half* __restrict__ Res, int Nc, int Kd, int bm, int bn)
{
    const int tid  = threadIdx.x;
    const int warp = tid >> 5;
    const int lane = tid & 31;

    const int wm = (warp >> 1) * 64;     // 4 warp rows
    const int wn = (warp & 1) * 64;      // 2 warp cols

    uint32_t sbase = (smem_u32(dynsmem) + 1023u) & ~1023u;

    float acc[4][8][4];
    #pragma unroll
    for (int mt = 0; mt < 4; mt++)
        #pragma unroll
        for (int nt = 0; nt < 8; nt++)
            #pragma unroll
            for (int r = 0; r < 4; r++) acc[mt][nt][r] = 0.f;

    const int nstg = Kd / 64;

    const int a_row_in = lane & 15;
    const int a_ch     = lane >> 4;
    const int b_n_in = (lane & 7) + ((lane >> 4) & 1) * 8;
    const int b_ch   = (lane >> 3) & 1;

    auto load_stage = [&](int s, int buf) {
        const uint32_t da = sbase + buf * STG_TOT;          // A: 32KB
        const uint32_t db = da + A_STG;                     // B: 16KB
        #pragma unroll
        for (int i = 0; i < 8; i++) {                       // A: 2048 chunks
            int c = tid + i * 256;
            int row = c >> 3, col16 = c & 7;
            uint32_t sw = sw128(row * 128 + col16 * 16);
            cp_async16(da + sw, A + (size_t)(bm + row) * Kd + s * 64 + col16 * 8);
        }
        #pragma unroll
        for (int i = 0; i < 4; i++) {                       // B: 1024 chunks
            int c = tid + i * 256;
            int row = c >> 3, col16 = c & 7;
            uint32_t sw = sw128(row * 128 + col16 * 16);
            cp_async16(db + sw, Bw + (size_t)(bn + row) * Kd + s * 64 + col16 * 8);
        }
        asm volatile("cp.async.commit_group;" ::: "memory");
    };

    load_stage(0, 0);
    load_stage(1, 1);

    int buf = 0;
    for (int s = 0; s < nstg; s++) {
        asm volatile("cp.async.wait_group 1;" ::: "memory");
        __syncthreads();

        if (s + 2 < nstg) {
            int nb = buf + 2; if (nb >= NPIPE) nb -= NPIPE;
            load_stage(s + 2, nb);
        } else {
            asm volatile("cp.async.commit_group;" ::: "memory");
        }

        const uint32_t abuf = sbase + buf * STG_TOT;
        const uint32_t bbuf = abuf + A_STG;

        uint32_t af[2][4][4], bfg[2][4][4];
        #pragma unroll
        for (int mt = 0; mt < 4; mt++) {
            uint32_t byte = (uint32_t)(wm + mt * 16 + a_row_in) * 128 + a_ch * 16;
            ldsm_x4(af[0][mt], abuf + sw128(byte));
        }
        #pragma unroll
        for (int nt2 = 0; nt2 < 4; nt2++) {
            uint32_t byte = (uint32_t)(wn + nt2 * 16 + b_n_in) * 128 + b_ch * 16;
            ldsm_x4(bfg[0][nt2], bbuf + sw128(byte));
        }

        #pragma unroll
        for (int ks = 0; ks < 4; ks++) {
            const int cur = ks & 1;
            if (ks < 3) {
                const int nxt = cur ^ 1;
                #pragma unroll
                for (int mt = 0; mt < 4; mt++) {
                    uint32_t byte = (uint32_t)(wm + mt * 16 + a_row_in) * 128
                                  + (ks + 1) * 32 + a_ch * 16;
                    ldsm_x4(af[nxt][mt], abuf + sw128(byte));
                }
                #pragma unroll
                for (int nt2 = 0; nt2 < 4; nt2++) {
                    uint32_t byte = (uint32_t)(wn + nt2 * 16 + b_n_in) * 128
                                  + (ks + 1) * 32 + b_ch * 16;
                    ldsm_x4(bfg[nxt][nt2], bbuf + sw128(byte));
                }
            }
            #pragma unroll
            for (int mt = 0; mt < 4; mt++)
                #pragma unroll
                for (int nt = 0; nt < 8; nt++)
                    mma_fp16(acc[mt][nt], af[cur][mt], &bfg[cur][nt >> 1][(nt & 1) * 2]);
        }

        buf++; if (buf == NPIPE) buf = 0;
    }

    // epilogue: bias (+ optional fp16 residual) + store
    const int g = lane >> 2;
    const int t = lane & 3;
    #pragma unroll
    for (int mt = 0; mt < 4; mt++) {
        int r = bm + wm + mt * 16 + g;
        #pragma unroll
        for (int nt = 0; nt < 8; nt++) {
            int cc = bn + wn + nt * 8 + 2 * t;
            float bi0 = bias[cc], bi1 = bias[cc + 1];
            float v00 = acc[mt][nt][0] + bi0, v01 = acc[mt][nt][1] + bi1;
            float v10 = acc[mt][nt][2] + bi0, v11 = acc[mt][nt][3] + bi1;
            if (Res) {
                float2 r0 = __half22float2(
                    *reinterpret_cast<const __half2*>(&Res[(size_t)r * Nc + cc]));
                float2 r1 = __half22float2(
                    *reinterpret_cast<const __half2*>(&Res[(size_t)(r + 8) * Nc + cc]));
                v00 += r0.x; v01 += r0.y; v10 += r1.x; v11 += r1.y;
            }
            if constexpr (sizeof(OutT) == 4) {
                *reinterpret_cast<float2*>(&C[(size_t)r * Nc + cc]) = make_float2(v00, v01);
                *reinterpret_cast<float2*>(&C[(size_t)(r + 8) * Nc + cc]) = make_float2(v10, v11);
            } else {
                __half2 h0 = __floats2half2_rn(v00, v01);
                __half2 h1 = __floats2half2_rn(v10, v11);
                *reinterpret_cast<__half2*>(&C[(size_t)r * Nc + cc])       = h0;
                *reinterpret_cast<__half2*>(&C[(size_t)(r + 8) * Nc + cc]) = h1;
            }
        }
    }
}

template <typename OutT>
__global__ __launch_bounds__(256, 1)
void gemm_h(const __half* __restrict__ A, const __half* __restrict__ Bw,
            const float* __restrict__ bias, OutT* __restrict__ C,
            const __half* __restrict__ Res, int Nc, int Kd)
{
    gemm_body<OutT>(A, Bw, bias, C, Res, Nc, Kd, blockIdx.y * 256, blockIdx.x * 128);
}

// fused QKV: blockIdx.x in [0,24): sel = x>>3 picks {W,b,C}, bn = (x&7)*128
__global__ __launch_bounds__(256, 1)
void gemm_qkv(const __half* __restrict__ A,
              const __half* __restrict__ W0, const __half* __restrict__ W1,
              const __half* __restrict__ W2,
              const float* __restrict__ b0, const float* __restrict__ b1,
              const float* __restrict__ b2,
              __half* __restrict__ C0, __half* __restrict__ C1,
              __half* __restrict__ C2, int Kd)
{
    const int sel = blockIdx.x >> 3;
    const __half* Bw  = (sel == 0) ? W0 : (sel == 1) ? W1 : W2;
    const float* bias = (sel == 0) ? b0 : (sel == 1) ? b1 : b2;
    __half* C         = (sel == 0) ? C0 : (sel == 1) ? C1 : C2;
    gemm_body<__half>(A, Bw, bias, C, nullptr, EDIM, Kd,
                      blockIdx.y * 256, (blockIdx.x & 7) * 128);
}

// ---------------- register-resident 6x6 attention ----------------
__global__ __launch_bounds__(256)
void attn_reg_kernel(const __half* __restrict__ Q, const __half* __restrict__ Kb,
                     const __half* __restrict__ V, __half* __restrict__ CTX)
{
    const int n    = blockIdx.x;
    const int warp = threadIdx.x >> 5;
    const int lane = threadIdx.x & 31;
    const int h    = blockIdx.y * 8 + warp;
    const int col  = h * HDIM + 2 * lane;

    float2 qf[NST], kf[NST];
    #pragma unroll
    for (int j = 0; j < NST; j++) {
        size_t base = ((size_t)j * NTOK + n) * EDIM + col;
        qf[j] = __half22float2(*reinterpret_cast<const __half2*>(Q + base));
        kf[j] = __half22float2(*reinterpret_cast<const __half2*>(Kb + base));
    }

    float p[36];
    #pragma unroll
    for (int qi = 0; qi < NST; qi++)
        #pragma unroll
        for (int ki = 0; ki < NST; ki++)
            p[qi * 6 + ki] = qf[qi].x * kf[ki].x + qf[qi].y * kf[ki].y;

    #pragma unroll
    for (int off = 16; off > 0; off >>= 1)
        #pragma unroll
        for (int i = 0; i < 36; i++)
            p[i] += __shfl_xor_sync(0xffffffffu, p[i], off);

    #pragma unroll
    for (int qi = 0; qi < NST; qi++) {
        float m = -1e30f;
        #pragma unroll
        for (int ki = 0; ki < NST; ki++) {
            p[qi * 6 + ki] *= 0.125f;
            m = fmaxf(m, p[qi * 6 + ki]);
        }
        float ssum = 0.f;
        #pragma unroll
        for (int ki = 0; ki < NST; ki++) {
            p[qi * 6 + ki] = __expf(p[qi * 6 + ki] - m);
            ssum += p[qi * 6 + ki];
        }
        float inv = 1.f / ssum;
        #pragma unroll
        for (int ki = 0; ki < NST; ki++) p[qi * 6 + ki] *= inv;
    }

    float2 vf[NST];
    #pragma unroll
    for (int j = 0; j < NST; j++) {
        size_t base = ((size_t)j * NTOK + n) * EDIM + col;
        vf[j] = __half22float2(*reinterpret_cast<const __half2*>(V + base));
    }
    #pragma unroll
    for (int qi = 0; qi < NST; qi++) {
        float cx = 0.f, cy = 0.f;
        #pragma unroll
        for (int ki = 0; ki < NST; ki++) {
            cx += p[qi * 6 + ki] * vf[ki].x;
            cy += p[qi * 6 + ki] * vf[ki].y;
        }
        size_t base = ((size_t)qi * NTOK + n) * EDIM + col;
        *reinterpret_cast<__half2*>(CTX + base) = __floats2half2_rn(cx, cy);
    }
}

// ---------------- block reduction helper (256 threads) ----------------
__device__ __forceinline__ float block_sum(float v, float* sbuf)
{
    const int lane = threadIdx.x & 31;
    const int wid  = threadIdx.x >> 5;
    #pragma unroll
    for (int o = 16; o > 0; o >>= 1) v += __shfl_xor_sync(0xffffffffu, v, o);
    if (lane == 0) sbuf[wid] = v;
    __syncthreads();
    if (wid == 0) {
        float r = (lane < 8) ? sbuf[lane] : 0.f;
        #pragma unroll
        for (int o = 4; o > 0; o >>= 1) r += __shfl_xor_sync(0xffffffffu, r, o);
        if (lane == 0) sbuf[0] = r;
    }
    __syncthreads();
    float r = sbuf[0];
    __syncthreads();
    return r;
}

// ---------------- LN1 + softmax(fusion_w)-weighted sum ----------------
// ATT already contains residual (fused in Wo epilogue). fp16 in, fp32 math.
__global__ __launch_bounds__(256)
void ln1_fuse_kernel(const __half* __restrict__ ATT,
                     const float* __restrict__ g1, const float* __restrict__ b1,
                     const float* __restrict__ fw, __half* __restrict__ FUSED)
{
    __shared__ float sbuf[32];
    const int n = blockIdx.x, tid = threadIdx.x;
    const __half2* A2 = reinterpret_cast<const __half2*>(ATT);
    __half2* F2 = reinterpret_cast<__half2*>(FUSED);

    float w[6];
    {
        float m = -1e30f;
        #pragma unroll
        for (int j = 0; j < 6; j++) { w[j] = fw[j]; m = fmaxf(m, w[j]); }
        float s = 0.f;
        #pragma unroll
        for (int j = 0; j < 6; j++) { w[j] = __expf(w[j] - m); s += w[j]; }
        float inv = 1.f / s;
        #pragma unroll
        for (int j = 0; j < 6; j++) w[j] *= inv;
    }

    const int e00 = 2 * tid,         e01 = e00 + 1;
    const int e10 = 2 * (tid + 256), e11 = e10 + 1;
    const float g1v[4] = { g1[e00], g1[e01], g1[e10], g1[e11] };
    const float b1v[4] = { b1[e00], b1[e01], b1[e10], b1[e11] };

    float accv[4] = {0.f, 0.f, 0.f, 0.f};
    for (int j = 0; j < 6; j++) {
        size_t b2 = ((size_t)j * NTOK + n) * (EDIM / 2);
        float2 a0 = __half22float2(A2[b2 + tid]);
        float2 a1 = __half22float2(A2[b2 + 256 + tid]);
        float x[4] = { a0.x, a0.y, a1.x, a1.y };
        float lsum = x[0] + x[1] + x[2] + x[3];
        float mean = block_sum(lsum, sbuf) * (1.f / EDIM);
        float lvar = 0.f;
        #pragma unroll
        for (int tq = 0; tq < 4; tq++) { float d = x[tq] - mean; lvar += d * d; }
        float var = block_sum(lvar, sbuf) * (1.f / EDIM);
        float inv = rsqrtf(var + LN_EPS);
        #pragma unroll
        for (int tq = 0; tq < 4; tq++)
            accv[tq] += w[j] * ((x[tq] - mean) * inv * g1v[tq] + b1v[tq]);
    }
    F2[(size_t)n * (EDIM / 2) + tid]       = __floats2half2_rn(accv[0], accv[1]);
    F2[(size_t)n * (EDIM / 2) + 256 + tid] = __floats2half2_rn(accv[2], accv[3]);
}

// ---------------- LeakyReLU + LN2 (in-place on d_out) ----------------
__global__ __launch_bounds__(256)
void lrelu_ln2_kernel(float* __restrict__ O, const float* __restrict__ g2,
                      const float* __restrict__ b2)
{
    __shared__ float sbuf[32];
    const int n = blockIdx.x, tid = threadIdx.x;
    size_t base = (size_t)n * HIDD;

    float x[4], lsum = 0.f;
    #pragma unroll
    for (int tq = 0; tq < 4; tq++) {
        int e = tq * 256 + tid;
        float v = O[base + e];
        v = (v >= 0.f) ? v : 0.01f * v;
        x[tq] = v; lsum += v;
    }
    float mean = block_sum(lsum, sbuf) * (1.f / HIDD);
    float lvar = 0.f;
    #pragma unroll
    for (int tq = 0; tq < 4; tq++) { float d = x[tq] - mean; lvar += d * d; }
    float var = block_sum(lvar, sbuf) * (1.f / HIDD);
    float inv = rsqrtf(var + LN_EPS);
    #pragma unroll
    for (int tq = 0; tq < 4; tq++) {
        int e = tq * 256 + tid;
        O[base + e] = (x[tq] - mean) * inv * g2[e] + b2[e];
    }
}

// ---------------- launch ----------------
extern "C" void kernel_launch(void* const* d_in, const int* in_sizes, int n_in,
                              void* d_out, int out_size)
{
    const float* st = (const float*)d_in[0];
    const float* Wq = (const float*)d_in[1];  const float* bq = (const float*)d_in[2];
    const float* Wk = (const float*)d_in[3];  const float* bk = (const float*)d_in[4];
    const float* Wv = (const float*)d_in[5];  const float* bv = (const float*)d_in[6];
    const float* Wo = (const float*)d_in[7];  const float* bo = (const float*)d_in[8];
    const float* g1 = (const float*)d_in[9];  const float* b1 = (const float*)d_in[10];
    const float* fw = (const float*)d_in[11];
    const float* Wf = (const float*)d_in[12]; const float* bf = (const float*)d_in[13];
    const float* g2 = (const float*)d_in[14]; const float* b2 = (const float*)d_in[15];
    float* out = (float*)d_out;

    __half *Qh, *Kh, *Vh, *ATTh, *STh, *CTXh, *FUSh, *Wqh, *Wkh, *Wvh, *Woh, *Wfh;
    cudaGetSymbolAddress((void**)&Qh,   g_Qh);
    cudaGetSymbolAddress((void**)&Kh,   g_Kh);
    cudaGetSymbolAddress((void**)&Vh,   g_Vh);
    cudaGetSymbolAddress((void**)&ATTh, g_ATTh);
    cudaGetSymbolAddress((void**)&STh,  g_STh);
    cudaGetSymbolAddress((void**)&CTXh, g_CTXh);
    cudaGetSymbolAddress((void**)&FUSh, g_FUSEDh);
    cudaGetSymbolAddress((void**)&Wqh,  g_Wqh);
    cudaGetSymbolAddress((void**)&Wkh,  g_Wkh);
    cudaGetSymbolAddress((void**)&Wvh,  g_Wvh);
    cudaGetSymbolAddress((void**)&Woh,  g_Woh);
    cudaGetSymbolAddress((void**)&Wfh,  g_Wfh);

    cudaFuncSetAttribute(gemm_h<__half>, cudaFuncAttributeMaxDynamicSharedMemorySize,
                         GEMMH_SMEM);
    cudaFuncSetAttribute(gemm_h<float>, cudaFuncAttributeMaxDynamicSharedMemorySize,
                         GEMMH_SMEM);
    cudaFuncSetAttribute(gemm_qkv, cudaFuncAttributeMaxDynamicSharedMemorySize,
                         GEMMH_SMEM);

    // ---- fused fp32 -> fp16 conversion (one launch) ----
    {
        const unsigned nst4 = (NROWS * EDIM) / 4;     // 12,582,912
        const unsigned w4   = (EDIM * EDIM) / 4;      // 262,144
        F2HBatch b;
        unsigned cum = 0;
        const float* srcs[6] = { st, Wq, Wk, Wv, Wo, Wf };
        __half* dsts[6] = { STh, Wqh, Wkh, Wvh, Woh, Wfh };
        unsigned lens[6] = { nst4, w4, w4, w4, w4, (HIDD * EDIM) / 4 };
        for (int s = 0; s < 6; s++) {
            b.seg[s].src = (const float4*)srcs[s];
            b.seg[s].dst = (uint2*)dsts[s];
            cum += lens[s];
            b.seg[s].end = cum;
        }
        f2h_multi<<<(cum + 255) / 256, 256>>>(b, cum);
    }

    dim3 blk(256);

    // fused Q/K/V projections: grid (24, 192)
    gemm_qkv<<<dim3(24, NROWS / 256), blk, GEMMH_SMEM>>>(
        STh, Wqh, Wkh, Wvh, bq, bk, bv, Qh, Kh, Vh, EDIM);

    attn_reg_kernel<<<dim3(NTOK, 2), 256>>>(Qh, Kh, Vh, CTXh);

    // Wo projection with fused residual (+STh)
    gemm_h<__half><<<dim3(8, NROWS / 256), blk, GEMMH_SMEM>>>(
        CTXh, Woh, bo, ATTh, STh, EDIM, EDIM);

    ln1_fuse_kernel<<<NTOK, 256>>>(ATTh, g1, b1, fw, FUSh);

    gemm_h<float><<<dim3(8, NTOK / 256), blk, GEMMH_SMEM>>>(
        FUSh, Wfh, bf, out, nullptr, HIDD, EDIM);

    lrelu_ln2_kernel<<<NTOK, 256>>>(out, g2, b2);
}